// round 3
// baseline (speedup 1.0000x reference)
#include <cuda_runtime.h>
#include <cstdint>

// Problem constants
#define Bsz 2
#define Ssz 2048
#define Esz 1024
#define Hsz 16
#define HDd 64
#define Msz (Bsz * Ssz)      // 4096 rows
#define NQKV (3 * Esz)       // 3072

// Scratch: head-split Q/K/V and attention output, each [B*H, S, HD]
__device__ float g_q[Bsz * Hsz * Ssz * HDd];
__device__ float g_k[Bsz * Hsz * Ssz * HDd];
__device__ float g_v[Bsz * Hsz * Ssz * HDd];
__device__ float g_o[Bsz * Hsz * Ssz * HDd];

// ---------------------------------------------------------------------------
// tf32 helpers (base ISA: mma.sync m16n8k8 tf32, sm_80+, works on sm_103)
// ---------------------------------------------------------------------------
__device__ __forceinline__ uint32_t f2tf32(float x) {
    uint32_t r;
    asm("cvt.rna.tf32.f32 %0, %1;" : "=r"(r) : "f"(x));
    return r;
}

__device__ __forceinline__ void split_tf32(float x, uint32_t& hi, uint32_t& lo) {
    hi = f2tf32(x);
    lo = f2tf32(x - __uint_as_float(hi));
}

__device__ __forceinline__ void mma8(float* d, const uint32_t* a, const uint32_t* b) {
    asm volatile(
        "mma.sync.aligned.m16n8k8.row.col.f32.tf32.tf32.f32 "
        "{%0,%1,%2,%3}, {%4,%5,%6,%7}, {%8,%9}, {%0,%1,%2,%3};"
        : "+f"(d[0]), "+f"(d[1]), "+f"(d[2]), "+f"(d[3])
        : "r"(a[0]), "r"(a[1]), "r"(a[2]), "r"(a[3]), "r"(b[0]), "r"(b[1]));
}

// Shared GEMM geometry: CTA 128x128, BK=32, 256 threads = 8 warps (2m x 4n),
// warp tile 64x32 -> 4 mtiles x 4 ntiles of m16n8k8.
// Padded smem strides: A row stride 36 floats, B row stride 132 floats.
#define ASTRIDE 36
#define BSTRIDE 132

struct Frag {
    float acc[4][4][4];
    int lane, wm0, wn0;
};

__device__ __forceinline__ void frag_init(Frag& f) {
    const int tid = threadIdx.x;
    const int wid = tid >> 5;
    f.lane = tid & 31;
    f.wm0 = (wid >> 2) * 64;
    f.wn0 = (wid & 3) * 32;
#pragma unroll
    for (int i = 0; i < 4; i++)
#pragma unroll
        for (int j = 0; j < 4; j++)
#pragma unroll
            for (int r = 0; r < 4; r++) f.acc[i][j][r] = 0.f;
}

// One BK=32 tile of 3xTF32 MMAs out of smem
__device__ __forceinline__ void gemm_tile(Frag& f, const float* As, const float* Bs) {
    const int g = f.lane >> 2;       // 0..7
    const int t = f.lane & 3;        // 0..3
#pragma unroll
    for (int ks = 0; ks < 4; ks++) {
        const int kb = ks * 8;
        uint32_t Ah[4][4], Al[4][4], Bh[4][2], Bl[4][2];
#pragma unroll
        for (int i = 0; i < 4; i++) {
            const int rb = f.wm0 + i * 16 + g;
            const float x0 = As[rb * ASTRIDE + kb + t];
            const float x1 = As[(rb + 8) * ASTRIDE + kb + t];
            const float x2 = As[rb * ASTRIDE + kb + t + 4];
            const float x3 = As[(rb + 8) * ASTRIDE + kb + t + 4];
            split_tf32(x0, Ah[i][0], Al[i][0]);
            split_tf32(x1, Ah[i][1], Al[i][1]);
            split_tf32(x2, Ah[i][2], Al[i][2]);
            split_tf32(x3, Ah[i][3], Al[i][3]);
        }
#pragma unroll
        for (int j = 0; j < 4; j++) {
            const int n = f.wn0 + j * 8 + g;
            const float y0 = Bs[(kb + t) * BSTRIDE + n];
            const float y1 = Bs[(kb + t + 4) * BSTRIDE + n];
            split_tf32(y0, Bh[j][0], Bl[j][0]);
            split_tf32(y1, Bh[j][1], Bl[j][1]);
        }
#pragma unroll
        for (int i = 0; i < 4; i++)
#pragma unroll
            for (int j = 0; j < 4; j++) {
                mma8(f.acc[i][j], Ah[i], Bh[j]);
                mma8(f.acc[i][j], Ah[i], Bl[j]);
                mma8(f.acc[i][j], Al[i], Bh[j]);
            }
    }
}

// ---------------------------------------------------------------------------
// Kernel 1: qkv = x @ w_qkv + b_qkv, scattered into head-split Q/K/V.
// grid = (NQKV/128, Msz/128), 256 threads.
// ---------------------------------------------------------------------------
__global__ __launch_bounds__(256) void qkv_tc(const float* __restrict__ X,
                                              const float* __restrict__ W,
                                              const float* __restrict__ bias) {
    __shared__ float As[128 * ASTRIDE];
    __shared__ float Bs[32 * BSTRIDE];
    const int tid = threadIdx.x;
    const int m0 = blockIdx.y * 128, n0 = blockIdx.x * 128;

    Frag f;
    frag_init(f);

    for (int k0 = 0; k0 < Esz; k0 += 32) {
        __syncthreads();
#pragma unroll
        for (int g = 0; g < 4; g++) {
            const int fi = g * 256 + tid;
            const int row = fi >> 3, cg = fi & 7;
            *(float4*)&As[row * ASTRIDE + cg * 4] =
                *(const float4*)(X + (m0 + row) * Esz + k0 + cg * 4);
        }
#pragma unroll
        for (int g = 0; g < 4; g++) {
            const int fi = g * 256 + tid;
            const int k = fi >> 5, n4 = fi & 31;
            *(float4*)&Bs[k * BSTRIDE + n4 * 4] =
                *(const float4*)(W + (k0 + k) * NQKV + n0 + n4 * 4);
        }
        __syncthreads();
        gemm_tile(f, As, Bs);
    }

    // Epilogue: bias + scatter to g_q/g_k/g_v
    const int g = f.lane >> 2, t = f.lane & 3;
#pragma unroll
    for (int i = 0; i < 4; i++) {
#pragma unroll
        for (int j = 0; j < 4; j++) {
#pragma unroll
            for (int r = 0; r < 4; r++) {
                const int row = m0 + f.wm0 + i * 16 + g + ((r >> 1) ? 8 : 0);
                const int col = n0 + f.wn0 + j * 8 + t * 2 + (r & 1);
                const float v = f.acc[i][j][r] + bias[col];
                const int b = row >> 11, sq = row & 2047;
                const int part = col >> 10;
                const int e = col & 1023;
                const int h = e >> 6, d = e & 63;
                float* dst = (part == 0) ? g_q : (part == 1) ? g_k : g_v;
                dst[(((b << 4) + h) * Ssz + sq) * HDd + d] = v;
            }
        }
    }
}

// ---------------------------------------------------------------------------
// Kernel 3: out = mergeheads(g_o) @ w_proj + b_proj.
// grid = (Esz/128, Msz/128), 256 threads.
// ---------------------------------------------------------------------------
__global__ __launch_bounds__(256) void proj_tc(const float* __restrict__ W,
                                               const float* __restrict__ bias,
                                               float* __restrict__ out) {
    __shared__ float As[128 * ASTRIDE];
    __shared__ float Bs[32 * BSTRIDE];
    const int tid = threadIdx.x;
    const int m0 = blockIdx.y * 128, n0 = blockIdx.x * 128;

    Frag f;
    frag_init(f);

    for (int k0 = 0; k0 < Esz; k0 += 32) {
        const int h = k0 >> 6, dbase = k0 & 63;
        __syncthreads();
#pragma unroll
        for (int g = 0; g < 4; g++) {
            const int fi = g * 256 + tid;
            const int row = fi >> 3, cg = fi & 7;
            const int gr = m0 + row;
            const int b = gr >> 11, sq = gr & 2047;
            *(float4*)&As[row * ASTRIDE + cg * 4] =
                *(const float4*)(g_o + (((b << 4) + h) * Ssz + sq) * HDd + dbase + cg * 4);
        }
#pragma unroll
        for (int g = 0; g < 4; g++) {
            const int fi = g * 256 + tid;
            const int k = fi >> 5, n4 = fi & 31;
            *(float4*)&Bs[k * BSTRIDE + n4 * 4] =
                *(const float4*)(W + (k0 + k) * Esz + n0 + n4 * 4);
        }
        __syncthreads();
        gemm_tile(f, As, Bs);
    }

    const int g = f.lane >> 2, t = f.lane & 3;
#pragma unroll
    for (int i = 0; i < 4; i++) {
#pragma unroll
        for (int j = 0; j < 4; j++) {
            const int r0 = m0 + f.wm0 + i * 16 + g;
            const int c0 = n0 + f.wn0 + j * 8 + t * 2;
            const float b0 = bias[c0], b1 = bias[c0 + 1];
            float2 v0 = make_float2(f.acc[i][j][0] + b0, f.acc[i][j][1] + b1);
            float2 v1 = make_float2(f.acc[i][j][2] + b0, f.acc[i][j][3] + b1);
            *(float2*)(out + r0 * Esz + c0) = v0;
            *(float2*)(out + (r0 + 8) * Esz + c0) = v1;
        }
    }
}

// ---------------------------------------------------------------------------
// Kernel 2: causal flash attention (round-1 proven version).
// grid = (S/64 q-tiles, B*H). 256 threads, 16x16, 4x4 fragments. 48KB smem.
// ---------------------------------------------------------------------------
__global__ __launch_bounds__(256) void attn_kernel() {
    __shared__ float Qs[64 * 64];
    __shared__ float Ks[64 * 64];   // K^T during score compute, then P
    __shared__ float Vs[64 * 64];

    const int tid = threadIdx.x;
    const int ty = tid >> 4;
    const int tx = tid & 15;
    const int bh = blockIdx.y;
    const int q0 = blockIdx.x * 64;

    const float* Qg = g_q + (bh * Ssz + q0) * HDd;
    const float* Kg = g_k + bh * Ssz * HDd;
    const float* Vg = g_v + bh * Ssz * HDd;

    {
        const int row = tid >> 2;
        const int db = (tid & 3) * 16;
#pragma unroll
        for (int ii = 0; ii < 4; ii++)
            *(float4*)&Qs[row * 64 + db + 4 * ii] =
                *(const float4*)(Qg + row * HDd + db + 4 * ii);
    }

    float m[4], l[4], o[4][4];
#pragma unroll
    for (int i = 0; i < 4; i++) {
        m[i] = -1e30f;
        l[i] = 0.f;
#pragma unroll
        for (int j = 0; j < 4; j++) o[i][j] = 0.f;
    }

    for (int kv0 = 0; kv0 <= q0; kv0 += 64) {
        __syncthreads();
        {
            const int row = tid >> 2;
            const int db = (tid & 3) * 16;
#pragma unroll
            for (int ii = 0; ii < 4; ii++) {
                float4 k4 = *(const float4*)(Kg + (kv0 + row) * HDd + db + 4 * ii);
                Ks[(db + 4 * ii + 0) * 64 + row] = k4.x;
                Ks[(db + 4 * ii + 1) * 64 + row] = k4.y;
                Ks[(db + 4 * ii + 2) * 64 + row] = k4.z;
                Ks[(db + 4 * ii + 3) * 64 + row] = k4.w;
                *(float4*)&Vs[row * 64 + db + 4 * ii] =
                    *(const float4*)(Vg + (kv0 + row) * HDd + db + 4 * ii);
            }
        }
        __syncthreads();

        float s[4][4];
#pragma unroll
        for (int i = 0; i < 4; i++)
#pragma unroll
            for (int j = 0; j < 4; j++) s[i][j] = 0.f;

#pragma unroll 4
        for (int d = 0; d < 64; d++) {
            float4 k4 = *(float4*)&Ks[d * 64 + tx * 4];
#pragma unroll
            for (int i = 0; i < 4; i++) {
                float q = Qs[(ty * 4 + i) * 64 + d];
                s[i][0] = fmaf(q, k4.x, s[i][0]);
                s[i][1] = fmaf(q, k4.y, s[i][1]);
                s[i][2] = fmaf(q, k4.z, s[i][2]);
                s[i][3] = fmaf(q, k4.w, s[i][3]);
            }
        }

        const float scale = 0.125f;
        if (kv0 == q0) {
#pragma unroll
            for (int i = 0; i < 4; i++) {
                const int qg = q0 + ty * 4 + i;
#pragma unroll
                for (int j = 0; j < 4; j++) {
                    const int kg = kv0 + tx * 4 + j;
                    s[i][j] = (kg <= qg) ? s[i][j] * scale : -1e30f;
                }
            }
        } else {
#pragma unroll
            for (int i = 0; i < 4; i++)
#pragma unroll
                for (int j = 0; j < 4; j++) s[i][j] *= scale;
        }

        float p[4][4];
#pragma unroll
        for (int i = 0; i < 4; i++) {
            float rmax = fmaxf(fmaxf(s[i][0], s[i][1]), fmaxf(s[i][2], s[i][3]));
#pragma unroll
            for (int off = 1; off < 16; off <<= 1)
                rmax = fmaxf(rmax, __shfl_xor_sync(0xffffffffu, rmax, off));
            const float mn = fmaxf(m[i], rmax);
            const float corr = __expf(m[i] - mn);
            float rs = 0.f;
#pragma unroll
            for (int j = 0; j < 4; j++) {
                p[i][j] = __expf(s[i][j] - mn);
                rs += p[i][j];
            }
#pragma unroll
            for (int off = 1; off < 16; off <<= 1)
                rs += __shfl_xor_sync(0xffffffffu, rs, off);
            l[i] = l[i] * corr + rs;
            m[i] = mn;
#pragma unroll
            for (int j = 0; j < 4; j++) o[i][j] *= corr;
        }

        __syncthreads();
#pragma unroll
        for (int i = 0; i < 4; i++)
#pragma unroll
            for (int j = 0; j < 4; j++)
                Ks[(ty * 4 + i) * 64 + tx * 4 + j] = p[i][j];
        __syncthreads();

#pragma unroll 2
        for (int k = 0; k < 64; k++) {
            float4 v4 = *(float4*)&Vs[k * 64 + tx * 4];
#pragma unroll
            for (int i = 0; i < 4; i++) {
                float pv = Ks[(ty * 4 + i) * 64 + k];
                o[i][0] = fmaf(pv, v4.x, o[i][0]);
                o[i][1] = fmaf(pv, v4.y, o[i][1]);
                o[i][2] = fmaf(pv, v4.z, o[i][2]);
                o[i][3] = fmaf(pv, v4.w, o[i][3]);
            }
        }
    }

    float* Og = g_o + (bh * Ssz + q0) * HDd;
#pragma unroll
    for (int i = 0; i < 4; i++) {
        const float inv = 1.f / l[i];
        float4 r4 = make_float4(o[i][0] * inv, o[i][1] * inv,
                                o[i][2] * inv, o[i][3] * inv);
        *(float4*)(Og + (ty * 4 + i) * HDd + tx * 4) = r4;
    }
}

// ---------------------------------------------------------------------------
extern "C" void kernel_launch(void* const* d_in, const int* in_sizes, int n_in,
                              void* d_out, int out_size) {
    const float* x = (const float*)d_in[0];
    const float* w_qkv = (const float*)d_in[1];
    const float* b_qkv = (const float*)d_in[2];
    const float* w_proj = (const float*)d_in[3];
    const float* b_proj = (const float*)d_in[4];
    float* out = (float*)d_out;

    qkv_tc<<<dim3(NQKV / 128, Msz / 128), 256>>>(x, w_qkv, b_qkv);
    attn_kernel<<<dim3(Ssz / 64, Bsz * Hsz), 256>>>();
    proj_tc<<<dim3(Esz / 128, Msz / 128), 256>>>(w_proj, b_proj, out);
}

// round 4
// speedup vs baseline: 1.5421x; 1.5421x over previous
#include <cuda_runtime.h>
#include <cuda_bf16.h>
#include <cstdint>

// Problem constants
#define Bsz 2
#define Ssz 2048
#define Esz 1024
#define Hsz 16
#define HDd 64
#define Msz (Bsz * Ssz)      // 4096 rows
#define NQKV (3 * Esz)       // 3072

// Scratch: head-split Q/K/V and attention output, each [B*H, S, HD]
__device__ float g_q[Bsz * Hsz * Ssz * HDd];
__device__ float g_k[Bsz * Hsz * Ssz * HDd];
__device__ float g_v[Bsz * Hsz * Ssz * HDd];
__device__ float g_o[Bsz * Hsz * Ssz * HDd];

// ---------------------------------------------------------------------------
// bf16 split helpers (bf16x3 emulated fp32 GEMM)
// ---------------------------------------------------------------------------
__device__ __forceinline__ void split2(float x0, float x1, uint32_t& hi, uint32_t& lo) {
    __nv_bfloat162 h = __floats2bfloat162_rn(x0, x1);
    float r0 = x0 - __bfloat162float(__low2bfloat16(h));
    float r1 = x1 - __bfloat162float(__high2bfloat16(h));
    __nv_bfloat162 l = __floats2bfloat162_rn(r0, r1);
    hi = *(uint32_t*)&h;
    lo = *(uint32_t*)&l;
}

__device__ __forceinline__ void split1(float x, uint16_t& h, uint16_t& l) {
    __nv_bfloat16 bh = __float2bfloat16_rn(x);
    __nv_bfloat16 bl = __float2bfloat16_rn(x - __bfloat162float(bh));
    h = *(uint16_t*)&bh;
    l = *(uint16_t*)&bl;
}

__device__ __forceinline__ void mma16(float* d, const uint32_t* a, const uint32_t* b) {
    asm volatile(
        "mma.sync.aligned.m16n8k16.row.col.f32.bf16.bf16.f32 "
        "{%0,%1,%2,%3}, {%4,%5,%6,%7}, {%8,%9}, {%0,%1,%2,%3};"
        : "+f"(d[0]), "+f"(d[1]), "+f"(d[2]), "+f"(d[3])
        : "r"(a[0]), "r"(a[1]), "r"(a[2]), "r"(a[3]), "r"(b[0]), "r"(b[1]));
}

// GEMM geometry: CTA 128x128, BK=32, 256 threads = 8 warps (2m x 4n),
// warp tile 64x32 -> 4 mtiles x 4 ntiles of m16n8k16 (2 k-steps per BK tile).
// smem tiles as uint32 (=bf16x2 k-pairs): [row][20] (16 pairs + 4 pad).
#define KP 20

// One BK=32 tile of bf16x3 MMAs out of pre-split smem
__device__ __forceinline__ void mma_bf16_tile(
    float acc[4][4][4],
    const uint32_t (*Ah)[KP], const uint32_t (*Al)[KP],
    const uint32_t (*Bh)[KP], const uint32_t (*Bl)[KP],
    int lane, int wm0, int wn0) {
    const int g = lane >> 2, t = lane & 3;
#pragma unroll
    for (int ks = 0; ks < 2; ks++) {
        const int c0 = ks * 8 + t, c1 = c0 + 4;
        uint32_t ah[4][4], al[4][4], bh[4][2], bl[4][2];
#pragma unroll
        for (int i = 0; i < 4; i++) {
            const int r0 = wm0 + i * 16 + g;
            ah[i][0] = Ah[r0][c0];     ah[i][1] = Ah[r0 + 8][c0];
            ah[i][2] = Ah[r0][c1];     ah[i][3] = Ah[r0 + 8][c1];
            al[i][0] = Al[r0][c0];     al[i][1] = Al[r0 + 8][c0];
            al[i][2] = Al[r0][c1];     al[i][3] = Al[r0 + 8][c1];
        }
#pragma unroll
        for (int j = 0; j < 4; j++) {
            const int n = wn0 + j * 8 + g;
            bh[j][0] = Bh[n][c0];  bh[j][1] = Bh[n][c1];
            bl[j][0] = Bl[n][c0];  bl[j][1] = Bl[n][c1];
        }
#pragma unroll
        for (int i = 0; i < 4; i++)
#pragma unroll
            for (int j = 0; j < 4; j++) {
                mma16(acc[i][j], ah[i], bh[j]);
                mma16(acc[i][j], ah[i], bl[j]);
                mma16(acc[i][j], al[i], bh[j]);
            }
    }
}

// Store A float4 (row, 4 consecutive k at cg*4) into split smem
__device__ __forceinline__ void store_a4(uint32_t (*Ah)[KP], uint32_t (*Al)[KP],
                                         int row, int cg, float4 v) {
    uint32_t h0, l0, h1, l1;
    split2(v.x, v.y, h0, l0);
    split2(v.z, v.w, h1, l1);
    Ah[row][cg * 2] = h0;  Ah[row][cg * 2 + 1] = h1;
    Al[row][cg * 2] = l0;  Al[row][cg * 2 + 1] = l1;
}

// Store B float4 (k fixed, 4 consecutive n at n4*4) transposed into split smem
__device__ __forceinline__ void store_b4(uint32_t (*Bh)[KP], uint32_t (*Bl)[KP],
                                         int k, int n4, float4 v) {
    const float vs[4] = {v.x, v.y, v.z, v.w};
    const int kp = k >> 1, kh = k & 1;
#pragma unroll
    for (int e = 0; e < 4; e++) {
        uint16_t h, l;
        split1(vs[e], h, l);
        ((uint16_t*)&Bh[n4 * 4 + e][kp])[kh] = h;
        ((uint16_t*)&Bl[n4 * 4 + e][kp])[kh] = l;
    }
}

// ---------------------------------------------------------------------------
// Kernel 1: qkv = x @ w_qkv + b_qkv, scattered into head-split Q/K/V.
// grid = (NQKV/128, Msz/128), 256 threads.
// ---------------------------------------------------------------------------
__global__ __launch_bounds__(256) void qkv_tc(const float* __restrict__ X,
                                              const float* __restrict__ W,
                                              const float* __restrict__ bias) {
    __shared__ uint32_t Ah[128][KP], Al[128][KP], Bh[128][KP], Bl[128][KP];
    const int tid = threadIdx.x;
    const int wid = tid >> 5, lane = tid & 31;
    const int wm0 = (wid >> 2) * 64, wn0 = (wid & 3) * 32;
    const int m0 = blockIdx.y * 128, n0 = blockIdx.x * 128;

    float acc[4][4][4];
#pragma unroll
    for (int i = 0; i < 4; i++)
#pragma unroll
        for (int j = 0; j < 4; j++)
#pragma unroll
            for (int r = 0; r < 4; r++) acc[i][j][r] = 0.f;

    const int aRow = tid >> 3, aCg = tid & 7;      // A: 128 rows x 8 float4
    const int bK = tid >> 5, bN4 = tid & 31;       // B: 32 k x 32 float4

    float4 aR[4], bR[4];
    // prologue: prefetch stage 0
#pragma unroll
    for (int g = 0; g < 4; g++) {
        aR[g] = *(const float4*)(X + (m0 + aRow + g * 32) * Esz + aCg * 4);
        bR[g] = *(const float4*)(W + (bK + g * 8) * NQKV + n0 + bN4 * 4);
    }

    for (int s = 0; s < Esz / 32; s++) {
        __syncthreads();   // previous MMA done reading smem
#pragma unroll
        for (int g = 0; g < 4; g++) {
            store_a4(Ah, Al, aRow + g * 32, aCg, aR[g]);
            store_b4(Bh, Bl, bK + g * 8, bN4, bR[g]);
        }
        __syncthreads();
        if (s + 1 < Esz / 32) {
            const int k0 = (s + 1) * 32;
#pragma unroll
            for (int g = 0; g < 4; g++) {
                aR[g] = *(const float4*)(X + (m0 + aRow + g * 32) * Esz + k0 + aCg * 4);
                bR[g] = *(const float4*)(W + (k0 + bK + g * 8) * NQKV + n0 + bN4 * 4);
            }
        }
        mma_bf16_tile(acc, Ah, Al, Bh, Bl, lane, wm0, wn0);
    }

    // Epilogue: bias + scatter to g_q/g_k/g_v
    const int g = lane >> 2, t = lane & 3;
#pragma unroll
    for (int i = 0; i < 4; i++) {
#pragma unroll
        for (int j = 0; j < 4; j++) {
#pragma unroll
            for (int r = 0; r < 4; r++) {
                const int row = m0 + wm0 + i * 16 + g + ((r >> 1) ? 8 : 0);
                const int col = n0 + wn0 + j * 8 + t * 2 + (r & 1);
                const float v = acc[i][j][r] + bias[col];
                const int b = row >> 11, sq = row & 2047;
                const int part = col >> 10;
                const int e = col & 1023;
                const int h = e >> 6, d = e & 63;
                float* dst = (part == 0) ? g_q : (part == 1) ? g_k : g_v;
                dst[(((b << 4) + h) * Ssz + sq) * HDd + d] = v;
            }
        }
    }
}

// ---------------------------------------------------------------------------
// Kernel 3: out = mergeheads(g_o) @ w_proj + b_proj.
// grid = (Esz/128, Msz/128), 256 threads.
// ---------------------------------------------------------------------------
__global__ __launch_bounds__(256) void proj_tc(const float* __restrict__ W,
                                               const float* __restrict__ bias,
                                               float* __restrict__ out) {
    __shared__ uint32_t Ah[128][KP], Al[128][KP], Bh[128][KP], Bl[128][KP];
    const int tid = threadIdx.x;
    const int wid = tid >> 5, lane = tid & 31;
    const int wm0 = (wid >> 2) * 64, wn0 = (wid & 3) * 32;
    const int m0 = blockIdx.y * 128, n0 = blockIdx.x * 128;

    float acc[4][4][4];
#pragma unroll
    for (int i = 0; i < 4; i++)
#pragma unroll
        for (int j = 0; j < 4; j++)
#pragma unroll
            for (int r = 0; r < 4; r++) acc[i][j][r] = 0.f;

    const int aRow = tid >> 3, aCg = tid & 7;
    const int bK = tid >> 5, bN4 = tid & 31;

    // A gather precompute: row -> (b, sq)
    int aOffBase[4];
#pragma unroll
    for (int g = 0; g < 4; g++) {
        const int gr = m0 + aRow + g * 32;
        const int b = gr >> 11, sq = gr & 2047;
        aOffBase[g] = ((b << 4) * Ssz + sq) * HDd;  // + h*S*HD + d
    }

    float4 aR[4], bR[4];
#pragma unroll
    for (int g = 0; g < 4; g++) {
        // k0 = 0 -> h=0, dbase=0
        aR[g] = *(const float4*)(g_o + aOffBase[g] + aCg * 4);
        bR[g] = *(const float4*)(W + (bK + g * 8) * Esz + n0 + bN4 * 4);
    }

    for (int s = 0; s < Esz / 32; s++) {
        __syncthreads();
#pragma unroll
        for (int g = 0; g < 4; g++) {
            store_a4(Ah, Al, aRow + g * 32, aCg, aR[g]);
            store_b4(Bh, Bl, bK + g * 8, bN4, bR[g]);
        }
        __syncthreads();
        if (s + 1 < Esz / 32) {
            const int k0 = (s + 1) * 32;
            const int h = k0 >> 6, dbase = k0 & 63;
#pragma unroll
            for (int g = 0; g < 4; g++) {
                aR[g] = *(const float4*)(g_o + aOffBase[g] + h * Ssz * HDd + dbase + aCg * 4);
                bR[g] = *(const float4*)(W + (k0 + bK + g * 8) * Esz + n0 + bN4 * 4);
            }
        }
        mma_bf16_tile(acc, Ah, Al, Bh, Bl, lane, wm0, wn0);
    }

    const int g = lane >> 2, t = lane & 3;
#pragma unroll
    for (int i = 0; i < 4; i++) {
#pragma unroll
        for (int j = 0; j < 4; j++) {
            const int r0 = m0 + wm0 + i * 16 + g;
            const int c0 = n0 + wn0 + j * 8 + t * 2;
            const float b0 = bias[c0], b1 = bias[c0 + 1];
            float2 v0 = make_float2(acc[i][j][0] + b0, acc[i][j][1] + b1);
            float2 v1 = make_float2(acc[i][j][2] + b0, acc[i][j][3] + b1);
            *(float2*)(out + r0 * Esz + c0) = v0;
            *(float2*)(out + (r0 + 8) * Esz + c0) = v1;
        }
    }
}

// ---------------------------------------------------------------------------
// Kernel 2: causal flash attention (proven FFMA version, unchanged).
// grid = (S/64 q-tiles, B*H). 256 threads, 16x16, 4x4 fragments. 48KB smem.
// ---------------------------------------------------------------------------
__global__ __launch_bounds__(256) void attn_kernel() {
    __shared__ float Qs[64 * 64];
    __shared__ float Ks[64 * 64];   // K^T during score compute, then P
    __shared__ float Vs[64 * 64];

    const int tid = threadIdx.x;
    const int ty = tid >> 4;
    const int tx = tid & 15;
    const int bh = blockIdx.y;
    const int q0 = blockIdx.x * 64;

    const float* Qg = g_q + (bh * Ssz + q0) * HDd;
    const float* Kg = g_k + bh * Ssz * HDd;
    const float* Vg = g_v + bh * Ssz * HDd;

    {
        const int row = tid >> 2;
        const int db = (tid & 3) * 16;
#pragma unroll
        for (int ii = 0; ii < 4; ii++)
            *(float4*)&Qs[row * 64 + db + 4 * ii] =
                *(const float4*)(Qg + row * HDd + db + 4 * ii);
    }

    float m[4], l[4], o[4][4];
#pragma unroll
    for (int i = 0; i < 4; i++) {
        m[i] = -1e30f;
        l[i] = 0.f;
#pragma unroll
        for (int j = 0; j < 4; j++) o[i][j] = 0.f;
    }

    for (int kv0 = 0; kv0 <= q0; kv0 += 64) {
        __syncthreads();
        {
            const int row = tid >> 2;
            const int db = (tid & 3) * 16;
#pragma unroll
            for (int ii = 0; ii < 4; ii++) {
                float4 k4 = *(const float4*)(Kg + (kv0 + row) * HDd + db + 4 * ii);
                Ks[(db + 4 * ii + 0) * 64 + row] = k4.x;
                Ks[(db + 4 * ii + 1) * 64 + row] = k4.y;
                Ks[(db + 4 * ii + 2) * 64 + row] = k4.z;
                Ks[(db + 4 * ii + 3) * 64 + row] = k4.w;
                *(float4*)&Vs[row * 64 + db + 4 * ii] =
                    *(const float4*)(Vg + (kv0 + row) * HDd + db + 4 * ii);
            }
        }
        __syncthreads();

        float s[4][4];
#pragma unroll
        for (int i = 0; i < 4; i++)
#pragma unroll
            for (int j = 0; j < 4; j++) s[i][j] = 0.f;

#pragma unroll 4
        for (int d = 0; d < 64; d++) {
            float4 k4 = *(float4*)&Ks[d * 64 + tx * 4];
#pragma unroll
            for (int i = 0; i < 4; i++) {
                float q = Qs[(ty * 4 + i) * 64 + d];
                s[i][0] = fmaf(q, k4.x, s[i][0]);
                s[i][1] = fmaf(q, k4.y, s[i][1]);
                s[i][2] = fmaf(q, k4.z, s[i][2]);
                s[i][3] = fmaf(q, k4.w, s[i][3]);
            }
        }

        const float scale = 0.125f;
        if (kv0 == q0) {
#pragma unroll
            for (int i = 0; i < 4; i++) {
                const int qg = q0 + ty * 4 + i;
#pragma unroll
                for (int j = 0; j < 4; j++) {
                    const int kg = kv0 + tx * 4 + j;
                    s[i][j] = (kg <= qg) ? s[i][j] * scale : -1e30f;
                }
            }
        } else {
#pragma unroll
            for (int i = 0; i < 4; i++)
#pragma unroll
                for (int j = 0; j < 4; j++) s[i][j] *= scale;
        }

        float p[4][4];
#pragma unroll
        for (int i = 0; i < 4; i++) {
            float rmax = fmaxf(fmaxf(s[i][0], s[i][1]), fmaxf(s[i][2], s[i][3]));
#pragma unroll
            for (int off = 1; off < 16; off <<= 1)
                rmax = fmaxf(rmax, __shfl_xor_sync(0xffffffffu, rmax, off));
            const float mn = fmaxf(m[i], rmax);
            const float corr = __expf(m[i] - mn);
            float rs = 0.f;
#pragma unroll
            for (int j = 0; j < 4; j++) {
                p[i][j] = __expf(s[i][j] - mn);
                rs += p[i][j];
            }
#pragma unroll
            for (int off = 1; off < 16; off <<= 1)
                rs += __shfl_xor_sync(0xffffffffu, rs, off);
            l[i] = l[i] * corr + rs;
            m[i] = mn;
#pragma unroll
            for (int j = 0; j < 4; j++) o[i][j] *= corr;
        }

        __syncthreads();
#pragma unroll
        for (int i = 0; i < 4; i++)
#pragma unroll
            for (int j = 0; j < 4; j++)
                Ks[(ty * 4 + i) * 64 + tx * 4 + j] = p[i][j];
        __syncthreads();

#pragma unroll 2
        for (int k = 0; k < 64; k++) {
            float4 v4 = *(float4*)&Vs[k * 64 + tx * 4];
#pragma unroll
            for (int i = 0; i < 4; i++) {
                float pv = Ks[(ty * 4 + i) * 64 + k];
                o[i][0] = fmaf(pv, v4.x, o[i][0]);
                o[i][1] = fmaf(pv, v4.y, o[i][1]);
                o[i][2] = fmaf(pv, v4.z, o[i][2]);
                o[i][3] = fmaf(pv, v4.w, o[i][3]);
            }
        }
    }

    float* Og = g_o + (bh * Ssz + q0) * HDd;
#pragma unroll
    for (int i = 0; i < 4; i++) {
        const float inv = 1.f / l[i];
        float4 r4 = make_float4(o[i][0] * inv, o[i][1] * inv,
                                o[i][2] * inv, o[i][3] * inv);
        *(float4*)(Og + (ty * 4 + i) * HDd + tx * 4) = r4;
    }
}

// ---------------------------------------------------------------------------
extern "C" void kernel_launch(void* const* d_in, const int* in_sizes, int n_in,
                              void* d_out, int out_size) {
    const float* x = (const float*)d_in[0];
    const float* w_qkv = (const float*)d_in[1];
    const float* b_qkv = (const float*)d_in[2];
    const float* w_proj = (const float*)d_in[3];
    const float* b_proj = (const float*)d_in[4];
    float* out = (float*)d_out;

    qkv_tc<<<dim3(NQKV / 128, Msz / 128), 256>>>(x, w_qkv, b_qkv);
    attn_kernel<<<dim3(Ssz / 64, Bsz * Hsz), 256>>>();
    proj_tc<<<dim3(Esz / 128, Msz / 128), 256>>>(w_proj, b_proj, out);
}

// round 5
// speedup vs baseline: 2.0892x; 1.3548x over previous
#include <cuda_runtime.h>
#include <cuda_bf16.h>
#include <cstdint>

// Problem constants
#define Bsz 2
#define Ssz 2048
#define Esz 1024
#define Hsz 16
#define HDd 64
#define Msz (Bsz * Ssz)      // 4096
#define NQKV (3 * Esz)       // 3072

// fp32 scratch: head-split Q/K/V and attention output
__device__ float g_q[Bsz * Hsz * Ssz * HDd];
__device__ float g_k[Bsz * Hsz * Ssz * HDd];
__device__ float g_v[Bsz * Hsz * Ssz * HDd];
__device__ float g_o[Bsz * Hsz * Ssz * HDd];

// bf16 hi/lo pre-split operands
__device__ __nv_bfloat16 sXh[Msz * Esz], sXl[Msz * Esz];            // [m][k]
__device__ __nv_bfloat16 sWqh[NQKV * Esz], sWql[NQKV * Esz];        // [n][k]
__device__ __nv_bfloat16 sWph[Esz * Esz], sWpl[Esz * Esz];          // [n][k]
__device__ __nv_bfloat16 sOh[Msz * Esz], sOl[Msz * Esz];            // [m][k] merged heads

// ---------------------------------------------------------------------------
// helpers
// ---------------------------------------------------------------------------
__device__ __forceinline__ void split2(float x0, float x1, uint32_t& hi, uint32_t& lo) {
    __nv_bfloat162 h = __floats2bfloat162_rn(x0, x1);
    float r0 = x0 - __bfloat162float(__low2bfloat16(h));
    float r1 = x1 - __bfloat162float(__high2bfloat16(h));
    __nv_bfloat162 l = __floats2bfloat162_rn(r0, r1);
    hi = *(uint32_t*)&h;
    lo = *(uint32_t*)&l;
}

__device__ __forceinline__ void mma16(float* d, const uint32_t* a, const uint32_t* b) {
    asm volatile(
        "mma.sync.aligned.m16n8k16.row.col.f32.bf16.bf16.f32 "
        "{%0,%1,%2,%3}, {%4,%5,%6,%7}, {%8,%9}, {%0,%1,%2,%3};"
        : "+f"(d[0]), "+f"(d[1]), "+f"(d[2]), "+f"(d[3])
        : "r"(a[0]), "r"(a[1]), "r"(a[2]), "r"(a[3]), "r"(b[0]), "r"(b[1]));
}

__device__ __forceinline__ void ldm4(uint32_t* r, uint32_t addr) {
    asm volatile("ldmatrix.sync.aligned.m8n8.x4.shared.b16 {%0,%1,%2,%3}, [%4];"
                 : "=r"(r[0]), "=r"(r[1]), "=r"(r[2]), "=r"(r[3]) : "r"(addr));
}

__device__ __forceinline__ void cp16(uint32_t dst, const void* src) {
    asm volatile("cp.async.cg.shared.global [%0], [%1], 16;"
                 :: "r"(dst), "l"(src));
}
#define CP_COMMIT() asm volatile("cp.async.commit_group;" ::: "memory")
#define CP_WAIT(n)  asm volatile("cp.async.wait_group %0;" :: "n"(n) : "memory")

__device__ __forceinline__ uint32_t smem_u32(const void* p) {
    uint32_t a;
    asm("{ .reg .u64 t; cvta.to.shared.u64 t, %1; cvt.u32.u64 %0, t; }"
        : "=r"(a) : "l"(p));
    return a;
}

// ---------------------------------------------------------------------------
// GEMM: CTA 128x128, BK=32, 256 threads = 8 warps (2m x 4n).
// smem tiles: 128 rows x 32 bf16, row pitch 80B (64B data + 16B pad ->
// ldmatrix-conflict-free). 4 tiles (Ah, Al, Bh, Bl) x 2 stages = 80KB dynamic.
// ---------------------------------------------------------------------------
#define TILE_B 10240            // 128 * 80
#define STAGE_B (4 * TILE_B)    // 40960
#define SMEM_DYN (2 * STAGE_B)  // 81920

__device__ __forceinline__ void load_stage(
    uint32_t sbst, const __nv_bfloat16* Ah, const __nv_bfloat16* Al,
    const __nv_bfloat16* Bh, const __nv_bfloat16* Bl,
    int m0, int n0, int k0, int tid) {
#pragma unroll
    for (int g = 0; g < 2; g++) {
        const int idx = g * 256 + tid;
        const int row = idx >> 2, ch = idx & 3;
        const uint32_t d = sbst + row * 80 + ch * 16;
        const int aoff = (m0 + row) * Esz + k0 + ch * 8;
        const int boff = (n0 + row) * Esz + k0 + ch * 8;
        cp16(d, Ah + aoff);
        cp16(d + TILE_B, Al + aoff);
        cp16(d + 2 * TILE_B, Bh + boff);
        cp16(d + 3 * TILE_B, Bl + boff);
    }
}

__device__ __forceinline__ void mma_stage(float acc[4][4][4], uint32_t sbst,
                                          int wm0, int wn0, int lane) {
    const int laneRowA = ((lane >> 3) & 1) * 8 + (lane & 7);
    const int chA = lane >> 4;
    const int laneRowB = (lane >> 4) * 8 + (lane & 7);
    const int chB = (lane >> 3) & 1;
#pragma unroll
    for (int ks = 0; ks < 2; ks++) {
        uint32_t ah[4][4], al[4][4], bh[2][4], bl[2][4];
#pragma unroll
        for (int i = 0; i < 4; i++) {
            const uint32_t ra =
                sbst + (wm0 + i * 16 + laneRowA) * 80 + (ks * 2 + chA) * 16;
            ldm4(ah[i], ra);
            ldm4(al[i], ra + TILE_B);
        }
#pragma unroll
        for (int jp = 0; jp < 2; jp++) {
            const uint32_t rb = sbst + 2 * TILE_B +
                (wn0 + jp * 16 + laneRowB) * 80 + (ks * 2 + chB) * 16;
            ldm4(bh[jp], rb);
            ldm4(bl[jp], rb + TILE_B);
        }
#pragma unroll
        for (int i = 0; i < 4; i++)
#pragma unroll
            for (int j = 0; j < 4; j++) {
                const uint32_t* BH_ = &bh[j >> 1][(j & 1) * 2];
                const uint32_t* BL_ = &bl[j >> 1][(j & 1) * 2];
                mma16(acc[i][j], ah[i], BH_);
                mma16(acc[i][j], ah[i], BL_);
                mma16(acc[i][j], al[i], BH_);
            }
    }
}

#define GEMM_MAINLOOP(Ah, Al, Bh, Bl)                                        \
    extern __shared__ char dsm[];                                            \
    const uint32_t sb = smem_u32(dsm);                                       \
    const int tid = threadIdx.x;                                             \
    const int wid = tid >> 5, lane = tid & 31;                               \
    const int wm0 = (wid >> 2) * 64, wn0 = (wid & 3) * 32;                   \
    const int m0 = blockIdx.y * 128, n0 = blockIdx.x * 128;                  \
    float acc[4][4][4];                                                      \
    _Pragma("unroll") for (int i = 0; i < 4; i++)                            \
        _Pragma("unroll") for (int j = 0; j < 4; j++)                        \
            _Pragma("unroll") for (int r = 0; r < 4; r++) acc[i][j][r] = 0.f;\
    load_stage(sb, Ah, Al, Bh, Bl, m0, n0, 0, tid);                          \
    CP_COMMIT();                                                             \
    for (int s = 0; s < Esz / 32; s++) {                                     \
        if (s + 1 < Esz / 32) {                                              \
            load_stage(sb + ((s + 1) & 1) * STAGE_B, Ah, Al, Bh, Bl,         \
                       m0, n0, (s + 1) * 32, tid);                           \
            CP_COMMIT();                                                     \
            CP_WAIT(1);                                                      \
        } else {                                                             \
            CP_WAIT(0);                                                      \
        }                                                                    \
        __syncthreads();                                                     \
        mma_stage(acc, sb + (s & 1) * STAGE_B, wm0, wn0, lane);              \
        __syncthreads();                                                     \
    }

// ---------------------------------------------------------------------------
// Kernel 1: qkv GEMM + scatter into head-split fp32 Q/K/V
// ---------------------------------------------------------------------------
__global__ __launch_bounds__(256) void gemm_qkv(const float* __restrict__ bias) {
    GEMM_MAINLOOP(sXh, sXl, sWqh, sWql)

    const int g = lane >> 2, t = lane & 3;
#pragma unroll
    for (int i = 0; i < 4; i++) {
#pragma unroll
        for (int j = 0; j < 4; j++) {
#pragma unroll
            for (int r = 0; r < 4; r++) {
                const int row = m0 + wm0 + i * 16 + g + ((r >> 1) ? 8 : 0);
                const int col = n0 + wn0 + j * 8 + t * 2 + (r & 1);
                const float v = acc[i][j][r] + bias[col];
                const int b = row >> 11, sq = row & 2047;
                const int part = col >> 10;
                const int e = col & 1023;
                const int h = e >> 6, d = e & 63;
                float* dst = (part == 0) ? g_q : (part == 1) ? g_k : g_v;
                dst[(((b << 4) + h) * Ssz + sq) * HDd + d] = v;
            }
        }
    }
}

// ---------------------------------------------------------------------------
// Kernel 3: proj GEMM -> d_out
// ---------------------------------------------------------------------------
__global__ __launch_bounds__(256) void gemm_proj(const float* __restrict__ bias,
                                                 float* __restrict__ out) {
    GEMM_MAINLOOP(sOh, sOl, sWph, sWpl)

    const int g = lane >> 2, t = lane & 3;
#pragma unroll
    for (int i = 0; i < 4; i++) {
#pragma unroll
        for (int j = 0; j < 4; j++) {
            const int r0 = m0 + wm0 + i * 16 + g;
            const int c0 = n0 + wn0 + j * 8 + t * 2;
            const float b0 = bias[c0], b1 = bias[c0 + 1];
            float2 v0 = make_float2(acc[i][j][0] + b0, acc[i][j][1] + b1);
            float2 v1 = make_float2(acc[i][j][2] + b0, acc[i][j][3] + b1);
            *(float2*)(out + r0 * Esz + c0) = v0;
            *(float2*)(out + (r0 + 8) * Esz + c0) = v1;
        }
    }
}

// ---------------------------------------------------------------------------
// Pre-split kernels
// ---------------------------------------------------------------------------
__global__ __launch_bounds__(256) void split_plain(const float4* __restrict__ src,
                                                   uint2* __restrict__ h2,
                                                   uint2* __restrict__ l2) {
    const int i = blockIdx.x * 256 + threadIdx.x;
    const float4 v = src[i];
    uint32_t h0, l0, h1, l1;
    split2(v.x, v.y, h0, l0);
    split2(v.z, v.w, h1, l1);
    h2[i] = make_uint2(h0, h1);
    l2[i] = make_uint2(l0, l1);
}

// W [K=1024][N] row-major -> Th/Tl [N][1024] bf16 (split + transpose)
__global__ __launch_bounds__(256) void split_w_tr(const float* __restrict__ W,
                                                  __nv_bfloat16* __restrict__ Th,
                                                  __nv_bfloat16* __restrict__ Tl,
                                                  int N) {
    __shared__ float t[32][33];
    const int k0 = blockIdx.y * 32, n0 = blockIdx.x * 32;
    const int tx = threadIdx.x & 31, ty = threadIdx.x >> 5;
#pragma unroll
    for (int r = ty; r < 32; r += 8)
        t[r][tx] = W[(k0 + r) * N + n0 + tx];
    __syncthreads();
#pragma unroll
    for (int r = ty; r < 32; r += 8) {
        const float v = t[tx][r];   // k = k0+tx, n = n0+r
        __nv_bfloat16 h = __float2bfloat16_rn(v);
        __nv_bfloat16 l = __float2bfloat16_rn(v - __bfloat162float(h));
        Th[(n0 + r) * Esz + k0 + tx] = h;
        Tl[(n0 + r) * Esz + k0 + tx] = l;
    }
}

// g_o head-split -> merged [m][k] bf16 hi/lo
__global__ __launch_bounds__(256) void split_go(uint2* __restrict__ h2,
                                                uint2* __restrict__ l2) {
    const int i = blockIdx.x * 256 + threadIdx.x;  // index of float4 in [4096][1024]
    const int m = i >> 8;
    const int kc = (i & 255) * 4;
    const int h = kc >> 6, d = kc & 63;
    const int b = m >> 11, s = m & 2047;
    const float4 v = *(const float4*)(g_o + (((b << 4) + h) * Ssz + s) * HDd + d);
    uint32_t h0, l0, h1, l1;
    split2(v.x, v.y, h0, l0);
    split2(v.z, v.w, h1, l1);
    h2[i] = make_uint2(h0, h1);
    l2[i] = make_uint2(l0, l1);
}

// ---------------------------------------------------------------------------
// Kernel 2: causal flash attention (proven FFMA version, unchanged).
// ---------------------------------------------------------------------------
__global__ __launch_bounds__(256) void attn_kernel() {
    __shared__ float Qs[64 * 64];
    __shared__ float Ks[64 * 64];
    __shared__ float Vs[64 * 64];

    const int tid = threadIdx.x;
    const int ty = tid >> 4;
    const int tx = tid & 15;
    const int bh = blockIdx.y;
    const int q0 = blockIdx.x * 64;

    const float* Qg = g_q + (bh * Ssz + q0) * HDd;
    const float* Kg = g_k + bh * Ssz * HDd;
    const float* Vg = g_v + bh * Ssz * HDd;

    {
        const int row = tid >> 2;
        const int db = (tid & 3) * 16;
#pragma unroll
        for (int ii = 0; ii < 4; ii++)
            *(float4*)&Qs[row * 64 + db + 4 * ii] =
                *(const float4*)(Qg + row * HDd + db + 4 * ii);
    }

    float m[4], l[4], o[4][4];
#pragma unroll
    for (int i = 0; i < 4; i++) {
        m[i] = -1e30f;
        l[i] = 0.f;
#pragma unroll
        for (int j = 0; j < 4; j++) o[i][j] = 0.f;
    }

    for (int kv0 = 0; kv0 <= q0; kv0 += 64) {
        __syncthreads();
        {
            const int row = tid >> 2;
            const int db = (tid & 3) * 16;
#pragma unroll
            for (int ii = 0; ii < 4; ii++) {
                float4 k4 = *(const float4*)(Kg + (kv0 + row) * HDd + db + 4 * ii);
                Ks[(db + 4 * ii + 0) * 64 + row] = k4.x;
                Ks[(db + 4 * ii + 1) * 64 + row] = k4.y;
                Ks[(db + 4 * ii + 2) * 64 + row] = k4.z;
                Ks[(db + 4 * ii + 3) * 64 + row] = k4.w;
                *(float4*)&Vs[row * 64 + db + 4 * ii] =
                    *(const float4*)(Vg + (kv0 + row) * HDd + db + 4 * ii);
            }
        }
        __syncthreads();

        float s[4][4];
#pragma unroll
        for (int i = 0; i < 4; i++)
#pragma unroll
            for (int j = 0; j < 4; j++) s[i][j] = 0.f;

#pragma unroll 4
        for (int d = 0; d < 64; d++) {
            float4 k4 = *(float4*)&Ks[d * 64 + tx * 4];
#pragma unroll
            for (int i = 0; i < 4; i++) {
                float q = Qs[(ty * 4 + i) * 64 + d];
                s[i][0] = fmaf(q, k4.x, s[i][0]);
                s[i][1] = fmaf(q, k4.y, s[i][1]);
                s[i][2] = fmaf(q, k4.z, s[i][2]);
                s[i][3] = fmaf(q, k4.w, s[i][3]);
            }
        }

        const float scale = 0.125f;
        if (kv0 == q0) {
#pragma unroll
            for (int i = 0; i < 4; i++) {
                const int qg = q0 + ty * 4 + i;
#pragma unroll
                for (int j = 0; j < 4; j++) {
                    const int kg = kv0 + tx * 4 + j;
                    s[i][j] = (kg <= qg) ? s[i][j] * scale : -1e30f;
                }
            }
        } else {
#pragma unroll
            for (int i = 0; i < 4; i++)
#pragma unroll
                for (int j = 0; j < 4; j++) s[i][j] *= scale;
        }

        float p[4][4];
#pragma unroll
        for (int i = 0; i < 4; i++) {
            float rmax = fmaxf(fmaxf(s[i][0], s[i][1]), fmaxf(s[i][2], s[i][3]));
#pragma unroll
            for (int off = 1; off < 16; off <<= 1)
                rmax = fmaxf(rmax, __shfl_xor_sync(0xffffffffu, rmax, off));
            const float mn = fmaxf(m[i], rmax);
            const float corr = __expf(m[i] - mn);
            float rs = 0.f;
#pragma unroll
            for (int j = 0; j < 4; j++) {
                p[i][j] = __expf(s[i][j] - mn);
                rs += p[i][j];
            }
#pragma unroll
            for (int off = 1; off < 16; off <<= 1)
                rs += __shfl_xor_sync(0xffffffffu, rs, off);
            l[i] = l[i] * corr + rs;
            m[i] = mn;
#pragma unroll
            for (int j = 0; j < 4; j++) o[i][j] *= corr;
        }

        __syncthreads();
#pragma unroll
        for (int i = 0; i < 4; i++)
#pragma unroll
            for (int j = 0; j < 4; j++)
                Ks[(ty * 4 + i) * 64 + tx * 4 + j] = p[i][j];
        __syncthreads();

#pragma unroll 2
        for (int k = 0; k < 64; k++) {
            float4 v4 = *(float4*)&Vs[k * 64 + tx * 4];
#pragma unroll
            for (int i = 0; i < 4; i++) {
                float pv = Ks[(ty * 4 + i) * 64 + k];
                o[i][0] = fmaf(pv, v4.x, o[i][0]);
                o[i][1] = fmaf(pv, v4.y, o[i][1]);
                o[i][2] = fmaf(pv, v4.z, o[i][2]);
                o[i][3] = fmaf(pv, v4.w, o[i][3]);
            }
        }
    }

    float* Og = g_o + (bh * Ssz + q0) * HDd;
#pragma unroll
    for (int i = 0; i < 4; i++) {
        const float inv = 1.f / l[i];
        float4 r4 = make_float4(o[i][0] * inv, o[i][1] * inv,
                                o[i][2] * inv, o[i][3] * inv);
        *(float4*)(Og + (ty * 4 + i) * HDd + tx * 4) = r4;
    }
}

// ---------------------------------------------------------------------------
extern "C" void kernel_launch(void* const* d_in, const int* in_sizes, int n_in,
                              void* d_out, int out_size) {
    const float* x = (const float*)d_in[0];
    const float* w_qkv = (const float*)d_in[1];
    const float* b_qkv = (const float*)d_in[2];
    const float* w_proj = (const float*)d_in[3];
    const float* b_proj = (const float*)d_in[4];
    float* out = (float*)d_out;

    static bool attr_done = false;
    if (!attr_done) {
        cudaFuncSetAttribute(gemm_qkv, cudaFuncAttributeMaxDynamicSharedMemorySize, SMEM_DYN);
        cudaFuncSetAttribute(gemm_proj, cudaFuncAttributeMaxDynamicSharedMemorySize, SMEM_DYN);
        attr_done = true;
    }

    __nv_bfloat16 *pXh, *pXl, *pWqh, *pWql, *pWph, *pWpl, *pOh, *pOl;
    cudaGetSymbolAddress((void**)&pXh, sXh);
    cudaGetSymbolAddress((void**)&pXl, sXl);
    cudaGetSymbolAddress((void**)&pWqh, sWqh);
    cudaGetSymbolAddress((void**)&pWql, sWql);
    cudaGetSymbolAddress((void**)&pWph, sWph);
    cudaGetSymbolAddress((void**)&pWpl, sWpl);
    cudaGetSymbolAddress((void**)&pOh, sOh);
    cudaGetSymbolAddress((void**)&pOl, sOl);

    split_plain<<<Msz * Esz / 4 / 256, 256>>>((const float4*)x, (uint2*)pXh, (uint2*)pXl);
    split_w_tr<<<dim3(NQKV / 32, Esz / 32), 256>>>(w_qkv, pWqh, pWql, NQKV);
    split_w_tr<<<dim3(Esz / 32, Esz / 32), 256>>>(w_proj, pWph, pWpl, Esz);
    gemm_qkv<<<dim3(NQKV / 128, Msz / 128), 256, SMEM_DYN>>>(b_qkv);
    attn_kernel<<<dim3(Ssz / 64, Bsz * Hsz), 256>>>();
    split_go<<<Msz * Esz / 4 / 256, 256>>>((uint2*)pOh, (uint2*)pOl);
    gemm_proj<<<dim3(Esz / 128, Msz / 128), 256, SMEM_DYN>>>(b_proj, out);
}

// round 6
// speedup vs baseline: 5.0608x; 2.4224x over previous
#include <cuda_runtime.h>
#include <cuda_bf16.h>
#include <cstdint>

// Problem constants
#define Bsz 2
#define Ssz 2048
#define Esz 1024
#define Hsz 16
#define HDd 64
#define Msz (Bsz * Ssz)      // 4096
#define NQKV (3 * Esz)       // 3072

// bf16 hi/lo pre-split operands for the dense GEMMs
__device__ __nv_bfloat16 sXh[Msz * Esz], sXl[Msz * Esz];            // [m][k]
__device__ __nv_bfloat16 sWqh[NQKV * Esz], sWql[NQKV * Esz];        // [n][k]
__device__ __nv_bfloat16 sWph[Esz * Esz], sWpl[Esz * Esz];          // [n][k]
__device__ __nv_bfloat16 sOh[Msz * Esz], sOl[Msz * Esz];            // [m][k] merged heads

// bf16 hi/lo head-split Q/K/V: [B*H][S][64] (Q pre-scaled by 0.125)
__device__ __nv_bfloat16 bQh[Bsz * Hsz * Ssz * HDd], bQl[Bsz * Hsz * Ssz * HDd];
__device__ __nv_bfloat16 bKh[Bsz * Hsz * Ssz * HDd], bKl[Bsz * Hsz * Ssz * HDd];
__device__ __nv_bfloat16 bVh[Bsz * Hsz * Ssz * HDd], bVl[Bsz * Hsz * Ssz * HDd];

// ---------------------------------------------------------------------------
// helpers
// ---------------------------------------------------------------------------
__device__ __forceinline__ void split2(float x0, float x1, uint32_t& hi, uint32_t& lo) {
    __nv_bfloat162 h = __floats2bfloat162_rn(x0, x1);
    float r0 = x0 - __bfloat162float(__low2bfloat16(h));
    float r1 = x1 - __bfloat162float(__high2bfloat16(h));
    __nv_bfloat162 l = __floats2bfloat162_rn(r0, r1);
    hi = *(uint32_t*)&h;
    lo = *(uint32_t*)&l;
}

__device__ __forceinline__ void mma16(float* d, const uint32_t* a, const uint32_t* b) {
    asm volatile(
        "mma.sync.aligned.m16n8k16.row.col.f32.bf16.bf16.f32 "
        "{%0,%1,%2,%3}, {%4,%5,%6,%7}, {%8,%9}, {%0,%1,%2,%3};"
        : "+f"(d[0]), "+f"(d[1]), "+f"(d[2]), "+f"(d[3])
        : "r"(a[0]), "r"(a[1]), "r"(a[2]), "r"(a[3]), "r"(b[0]), "r"(b[1]));
}

__device__ __forceinline__ void ldm4(uint32_t* r, uint32_t addr) {
    asm volatile("ldmatrix.sync.aligned.m8n8.x4.shared.b16 {%0,%1,%2,%3}, [%4];"
                 : "=r"(r[0]), "=r"(r[1]), "=r"(r[2]), "=r"(r[3]) : "r"(addr));
}

__device__ __forceinline__ void ldm4t(uint32_t* r, uint32_t addr) {
    asm volatile("ldmatrix.sync.aligned.m8n8.x4.trans.shared.b16 {%0,%1,%2,%3}, [%4];"
                 : "=r"(r[0]), "=r"(r[1]), "=r"(r[2]), "=r"(r[3]) : "r"(addr));
}

__device__ __forceinline__ void cp16(uint32_t dst, const void* src) {
    asm volatile("cp.async.cg.shared.global [%0], [%1], 16;"
                 :: "r"(dst), "l"(src));
}
#define CP_COMMIT() asm volatile("cp.async.commit_group;" ::: "memory")
#define CP_WAIT(n)  asm volatile("cp.async.wait_group %0;" :: "n"(n) : "memory")

__device__ __forceinline__ uint32_t smem_u32(const void* p) {
    uint32_t a;
    asm("{ .reg .u64 t; cvta.to.shared.u64 t, %1; cvt.u32.u64 %0, t; }"
        : "=r"(a) : "l"(p));
    return a;
}

// ---------------------------------------------------------------------------
// Dense GEMM machinery (unchanged from round 5): CTA 128x128, BK=32,
// 256 threads, pitch-80 smem, cp.async double buffer, ldmatrix, bf16x3.
// ---------------------------------------------------------------------------
#define TILE_B 10240            // 128 * 80
#define STAGE_B (4 * TILE_B)    // 40960
#define SMEM_DYN (2 * STAGE_B)  // 81920

__device__ __forceinline__ void load_stage(
    uint32_t sbst, const __nv_bfloat16* Ah, const __nv_bfloat16* Al,
    const __nv_bfloat16* Bh, const __nv_bfloat16* Bl,
    int m0, int n0, int k0, int tid) {
#pragma unroll
    for (int g = 0; g < 2; g++) {
        const int idx = g * 256 + tid;
        const int row = idx >> 2, ch = idx & 3;
        const uint32_t d = sbst + row * 80 + ch * 16;
        const int aoff = (m0 + row) * Esz + k0 + ch * 8;
        const int boff = (n0 + row) * Esz + k0 + ch * 8;
        cp16(d, Ah + aoff);
        cp16(d + TILE_B, Al + aoff);
        cp16(d + 2 * TILE_B, Bh + boff);
        cp16(d + 3 * TILE_B, Bl + boff);
    }
}

__device__ __forceinline__ void mma_stage(float acc[4][4][4], uint32_t sbst,
                                          int wm0, int wn0, int lane) {
    const int laneRowA = ((lane >> 3) & 1) * 8 + (lane & 7);
    const int chA = lane >> 4;
    const int laneRowB = (lane >> 4) * 8 + (lane & 7);
    const int chB = (lane >> 3) & 1;
#pragma unroll
    for (int ks = 0; ks < 2; ks++) {
        uint32_t ah[4][4], al[4][4], bh[2][4], bl[2][4];
#pragma unroll
        for (int i = 0; i < 4; i++) {
            const uint32_t ra =
                sbst + (wm0 + i * 16 + laneRowA) * 80 + (ks * 2 + chA) * 16;
            ldm4(ah[i], ra);
            ldm4(al[i], ra + TILE_B);
        }
#pragma unroll
        for (int jp = 0; jp < 2; jp++) {
            const uint32_t rb = sbst + 2 * TILE_B +
                (wn0 + jp * 16 + laneRowB) * 80 + (ks * 2 + chB) * 16;
            ldm4(bh[jp], rb);
            ldm4(bl[jp], rb + TILE_B);
        }
#pragma unroll
        for (int i = 0; i < 4; i++)
#pragma unroll
            for (int j = 0; j < 4; j++) {
                const uint32_t* BH_ = &bh[j >> 1][(j & 1) * 2];
                const uint32_t* BL_ = &bl[j >> 1][(j & 1) * 2];
                mma16(acc[i][j], ah[i], BH_);
                mma16(acc[i][j], ah[i], BL_);
                mma16(acc[i][j], al[i], BH_);
            }
    }
}

#define GEMM_MAINLOOP(Ah, Al, Bh, Bl)                                        \
    extern __shared__ char dsm[];                                            \
    const uint32_t sb = smem_u32(dsm);                                       \
    const int tid = threadIdx.x;                                             \
    const int wid = tid >> 5, lane = tid & 31;                               \
    const int wm0 = (wid >> 2) * 64, wn0 = (wid & 3) * 32;                   \
    const int m0 = blockIdx.y * 128, n0 = blockIdx.x * 128;                  \
    float acc[4][4][4];                                                      \
    _Pragma("unroll") for (int i = 0; i < 4; i++)                            \
        _Pragma("unroll") for (int j = 0; j < 4; j++)                        \
            _Pragma("unroll") for (int r = 0; r < 4; r++) acc[i][j][r] = 0.f;\
    load_stage(sb, Ah, Al, Bh, Bl, m0, n0, 0, tid);                          \
    CP_COMMIT();                                                             \
    for (int s = 0; s < Esz / 32; s++) {                                     \
        if (s + 1 < Esz / 32) {                                              \
            load_stage(sb + ((s + 1) & 1) * STAGE_B, Ah, Al, Bh, Bl,         \
                       m0, n0, (s + 1) * 32, tid);                           \
            CP_COMMIT();                                                     \
            CP_WAIT(1);                                                      \
        } else {                                                             \
            CP_WAIT(0);                                                      \
        }                                                                    \
        __syncthreads();                                                     \
        mma_stage(acc, sb + (s & 1) * STAGE_B, wm0, wn0, lane);              \
        __syncthreads();                                                     \
    }

// ---------------------------------------------------------------------------
// Kernel 1: qkv GEMM; epilogue writes pre-split bf16 Q/K/V (Q scaled 0.125)
// ---------------------------------------------------------------------------
__global__ __launch_bounds__(256) void gemm_qkv(const float* __restrict__ bias) {
    GEMM_MAINLOOP(sXh, sXl, sWqh, sWql)

    const int g2 = lane >> 2, t2 = lane & 3;
#pragma unroll
    for (int i = 0; i < 4; i++) {
#pragma unroll
        for (int j = 0; j < 4; j++) {
            const int r0 = m0 + wm0 + i * 16 + g2;
            const int c0 = n0 + wn0 + j * 8 + t2 * 2;
            const int part = c0 >> 10, e = c0 & 1023;
            const int hh = e >> 6, d = e & 63;
            __nv_bfloat16 *dh, *dl;
            if (part == 0)      { dh = bQh; dl = bQl; }
            else if (part == 1) { dh = bKh; dl = bKl; }
            else                { dh = bVh; dl = bVl; }
            const float sc = (part == 0) ? 0.125f : 1.f;
            const float bb0 = bias[c0], bb1 = bias[c0 + 1];
            {
                const int b = r0 >> 11, sq = r0 & 2047;
                const int off = (((b << 4) + hh) * Ssz + sq) * HDd + d;
                uint32_t hi, lo;
                split2((acc[i][j][0] + bb0) * sc, (acc[i][j][1] + bb1) * sc, hi, lo);
                *(uint32_t*)(dh + off) = hi;
                *(uint32_t*)(dl + off) = lo;
            }
            {
                const int r1 = r0 + 8;
                const int b = r1 >> 11, sq = r1 & 2047;
                const int off = (((b << 4) + hh) * Ssz + sq) * HDd + d;
                uint32_t hi, lo;
                split2((acc[i][j][2] + bb0) * sc, (acc[i][j][3] + bb1) * sc, hi, lo);
                *(uint32_t*)(dh + off) = hi;
                *(uint32_t*)(dl + off) = lo;
            }
        }
    }
}

// ---------------------------------------------------------------------------
// Kernel 3: proj GEMM -> d_out
// ---------------------------------------------------------------------------
__global__ __launch_bounds__(256) void gemm_proj(const float* __restrict__ bias,
                                                 float* __restrict__ out) {
    GEMM_MAINLOOP(sOh, sOl, sWph, sWpl)

    const int g2 = lane >> 2, t2 = lane & 3;
#pragma unroll
    for (int i = 0; i < 4; i++) {
#pragma unroll
        for (int j = 0; j < 4; j++) {
            const int r0 = m0 + wm0 + i * 16 + g2;
            const int c0 = n0 + wn0 + j * 8 + t2 * 2;
            const float b0 = bias[c0], b1 = bias[c0 + 1];
            float2 v0 = make_float2(acc[i][j][0] + b0, acc[i][j][1] + b1);
            float2 v1 = make_float2(acc[i][j][2] + b0, acc[i][j][3] + b1);
            *(float2*)(out + r0 * Esz + c0) = v0;
            *(float2*)(out + (r0 + 8) * Esz + c0) = v1;
        }
    }
}

// ---------------------------------------------------------------------------
// Pre-split kernels (X, weights)
// ---------------------------------------------------------------------------
__global__ __launch_bounds__(256) void split_plain(const float4* __restrict__ src,
                                                   uint2* __restrict__ h2,
                                                   uint2* __restrict__ l2) {
    const int i = blockIdx.x * 256 + threadIdx.x;
    const float4 v = src[i];
    uint32_t h0, l0, h1, l1;
    split2(v.x, v.y, h0, l0);
    split2(v.z, v.w, h1, l1);
    h2[i] = make_uint2(h0, h1);
    l2[i] = make_uint2(l0, l1);
}

__global__ __launch_bounds__(256) void split_w_tr(const float* __restrict__ W,
                                                  __nv_bfloat16* __restrict__ Th,
                                                  __nv_bfloat16* __restrict__ Tl,
                                                  int N) {
    __shared__ float t[32][33];
    const int k0 = blockIdx.y * 32, n0 = blockIdx.x * 32;
    const int tx = threadIdx.x & 31, ty = threadIdx.x >> 5;
#pragma unroll
    for (int r = ty; r < 32; r += 8)
        t[r][tx] = W[(k0 + r) * N + n0 + tx];
    __syncthreads();
#pragma unroll
    for (int r = ty; r < 32; r += 8) {
        const float v = t[tx][r];
        __nv_bfloat16 h = __float2bfloat16_rn(v);
        __nv_bfloat16 l = __float2bfloat16_rn(v - __bfloat162float(h));
        Th[(n0 + r) * Esz + k0 + tx] = h;
        Tl[(n0 + r) * Esz + k0 + tx] = l;
    }
}

// ---------------------------------------------------------------------------
// Kernel 2: tensor-core causal flash attention.
// grid = (32 q-tiles, 32 bh), 128 threads (4 warps; warp w owns q rows
// wq0=16w..16w+15 of its 64-row tile). kv tiles of 64, double-buffered.
// smem: Q hi/lo + 2 stages x (Kh,Kl,Vh,Vl), pitch 144B rows.
// ---------------------------------------------------------------------------
#define AT_PITCH 144
#define AT_TILE (64 * AT_PITCH)              // 9216
#define AT_STAGE0 (2 * AT_TILE)              // Q hi/lo before stages
#define AT_STAGE_B (4 * AT_TILE)             // 36864
#define AT_SMEM (AT_STAGE0 + 2 * AT_STAGE_B) // 92160

__device__ __forceinline__ void at_load_kv(uint32_t st, int base, int kv0, int tid) {
#pragma unroll
    for (int gq = 0; gq < 4; gq++) {
        const int idx = gq * 128 + tid;          // 0..511
        const int row = idx >> 3, ch = idx & 7;
        const uint32_t d = st + row * AT_PITCH + ch * 16;
        const int off = base + (kv0 + row) * HDd + ch * 8;
        cp16(d, bKh + off);
        cp16(d + AT_TILE, bKl + off);
        cp16(d + 2 * AT_TILE, bVh + off);
        cp16(d + 3 * AT_TILE, bVl + off);
    }
}

__global__ __launch_bounds__(128) void attn_tc() {
    extern __shared__ char dsm[];
    const uint32_t sb = smem_u32(dsm);
    const int tid = threadIdx.x, wid = tid >> 5, lane = tid & 31;
    const int bh = blockIdx.y, q0 = blockIdx.x * 64;
    const int wq0 = wid * 16;
    const int g = lane >> 2, t = lane & 3;
    const int base = bh * Ssz * HDd;

    // async: Q tile hi/lo
#pragma unroll
    for (int gq = 0; gq < 4; gq++) {
        const int idx = gq * 128 + tid;
        const int row = idx >> 3, ch = idx & 7;
        const uint32_t d = sb + row * AT_PITCH + ch * 16;
        const int off = base + (q0 + row) * HDd + ch * 8;
        cp16(d, bQh + off);
        cp16(d + AT_TILE, bQl + off);
    }
    at_load_kv(sb + AT_STAGE0, base, 0, tid);
    CP_COMMIT();

    const int T = q0 / 64 + 1;

    float oacc[8][4];
#pragma unroll
    for (int j = 0; j < 8; j++)
#pragma unroll
        for (int r = 0; r < 4; r++) oacc[j][r] = 0.f;
    float m_a = -1e30f, m_b = -1e30f, l_a = 0.f, l_b = 0.f;
    uint32_t qh[4][4], ql[4][4];

    const int laneRowB = (lane >> 4) * 8 + (lane & 7);
    const int chB = (lane >> 3) & 1;

    for (int tt = 0; tt < T; tt++) {
        if (tt + 1 < T) {
            at_load_kv(sb + AT_STAGE0 + ((tt + 1) & 1) * AT_STAGE_B,
                       base, (tt + 1) * 64, tid);
            CP_COMMIT();
            CP_WAIT(1);
        } else {
            CP_WAIT(0);
        }
        __syncthreads();

        if (tt == 0) {
#pragma unroll
            for (int ks = 0; ks < 4; ks++) {
                const uint32_t ra = sb + (wq0 + (lane & 15)) * AT_PITCH +
                                    (ks * 2 + (lane >> 4)) * 16;
                ldm4(qh[ks], ra);
                ldm4(ql[ks], ra + AT_TILE);
            }
        }

        const uint32_t st = sb + AT_STAGE0 + (tt & 1) * AT_STAGE_B;

        // S = Q K^T (bf16x3)
        float sacc[8][4];
#pragma unroll
        for (int j = 0; j < 8; j++)
#pragma unroll
            for (int r = 0; r < 4; r++) sacc[j][r] = 0.f;

#pragma unroll
        for (int jp = 0; jp < 4; jp++) {
#pragma unroll
            for (int ks = 0; ks < 4; ks++) {
                const uint32_t rb = st + (jp * 16 + laneRowB) * AT_PITCH +
                                    (ks * 2 + chB) * 16;
                uint32_t kh4[4], kl4[4];
                ldm4(kh4, rb);
                ldm4(kl4, rb + AT_TILE);
                mma16(sacc[jp * 2], qh[ks], &kh4[0]);
                mma16(sacc[jp * 2], qh[ks], &kl4[0]);
                mma16(sacc[jp * 2], ql[ks], &kh4[0]);
                mma16(sacc[jp * 2 + 1], qh[ks], &kh4[2]);
                mma16(sacc[jp * 2 + 1], qh[ks], &kl4[2]);
                mma16(sacc[jp * 2 + 1], ql[ks], &kh4[2]);
            }
        }

        const int rowa = q0 + wq0 + g;
        const int rowb = rowa + 8;

        // causal mask (diagonal tile only)
        if (tt == T - 1) {
            const int kvb = tt * 64;
#pragma unroll
            for (int j = 0; j < 8; j++) {
                const int c0 = kvb + j * 8 + t * 2;
                if (c0 > rowa) sacc[j][0] = -1e30f;
                if (c0 + 1 > rowa) sacc[j][1] = -1e30f;
                if (c0 > rowb) sacc[j][2] = -1e30f;
                if (c0 + 1 > rowb) sacc[j][3] = -1e30f;
            }
        }

        // online softmax
        float mxa = -1e30f, mxb = -1e30f;
#pragma unroll
        for (int j = 0; j < 8; j++) {
            mxa = fmaxf(mxa, fmaxf(sacc[j][0], sacc[j][1]));
            mxb = fmaxf(mxb, fmaxf(sacc[j][2], sacc[j][3]));
        }
        mxa = fmaxf(mxa, __shfl_xor_sync(0xffffffffu, mxa, 1));
        mxa = fmaxf(mxa, __shfl_xor_sync(0xffffffffu, mxa, 2));
        mxb = fmaxf(mxb, __shfl_xor_sync(0xffffffffu, mxb, 1));
        mxb = fmaxf(mxb, __shfl_xor_sync(0xffffffffu, mxb, 2));
        const float mna = fmaxf(m_a, mxa), mnb = fmaxf(m_b, mxb);
        const float ca = __expf(m_a - mna), cb = __expf(m_b - mnb);
        m_a = mna;
        m_b = mnb;

        float ra = 0.f, rb = 0.f;
        uint32_t ph[4][4], pl[4][4];
#pragma unroll
        for (int j = 0; j < 8; j++) {
            const float p0 = __expf(sacc[j][0] - mna);
            const float p1 = __expf(sacc[j][1] - mna);
            const float p2 = __expf(sacc[j][2] - mnb);
            const float p3 = __expf(sacc[j][3] - mnb);
            ra += p0 + p1;
            rb += p2 + p3;
            uint32_t h01, l01, h23, l23;
            split2(p0, p1, h01, l01);
            split2(p2, p3, h23, l23);
            const int ks = j >> 1, half = (j & 1) * 2;
            ph[ks][half] = h01;
            ph[ks][half + 1] = h23;
            pl[ks][half] = l01;
            pl[ks][half + 1] = l23;
        }
        ra += __shfl_xor_sync(0xffffffffu, ra, 1);
        ra += __shfl_xor_sync(0xffffffffu, ra, 2);
        rb += __shfl_xor_sync(0xffffffffu, rb, 1);
        rb += __shfl_xor_sync(0xffffffffu, rb, 2);
        l_a = l_a * ca + ra;
        l_b = l_b * cb + rb;

#pragma unroll
        for (int j = 0; j < 8; j++) {
            oacc[j][0] *= ca;
            oacc[j][1] *= ca;
            oacc[j][2] *= cb;
            oacc[j][3] *= cb;
        }

        // O += P V (bf16x3), V via trans-ldmatrix
        const uint32_t vbase = st + 2 * AT_TILE;
#pragma unroll
        for (int ks = 0; ks < 4; ks++) {
#pragma unroll
            for (int jp = 0; jp < 4; jp++) {
                const uint32_t va = vbase + (ks * 16 + (lane & 15)) * AT_PITCH +
                                    (jp * 16 + (lane >> 4) * 8) * 2;
                uint32_t vh4[4], vl4[4];
                ldm4t(vh4, va);
                ldm4t(vl4, va + AT_TILE);
                mma16(oacc[jp * 2], ph[ks], &vh4[0]);
                mma16(oacc[jp * 2], ph[ks], &vl4[0]);
                mma16(oacc[jp * 2], pl[ks], &vh4[0]);
                mma16(oacc[jp * 2 + 1], ph[ks], &vh4[2]);
                mma16(oacc[jp * 2 + 1], ph[ks], &vl4[2]);
                mma16(oacc[jp * 2 + 1], pl[ks], &vh4[2]);
            }
        }
        __syncthreads();
    }

    // normalize + write merged-head pre-split output
    const float ia = 1.f / l_a, ib = 1.f / l_b;
    const int b = bh >> 4, h = bh & 15;
    const int rowa = q0 + wq0 + g;
    const int moa = (b * Ssz + rowa) * Esz + h * HDd;
    const int mob = (b * Ssz + rowa + 8) * Esz + h * HDd;
#pragma unroll
    for (int j = 0; j < 8; j++) {
        const int d = j * 8 + t * 2;
        uint32_t h01, l01, h23, l23;
        split2(oacc[j][0] * ia, oacc[j][1] * ia, h01, l01);
        split2(oacc[j][2] * ib, oacc[j][3] * ib, h23, l23);
        *(uint32_t*)(sOh + moa + d) = h01;
        *(uint32_t*)(sOl + moa + d) = l01;
        *(uint32_t*)(sOh + mob + d) = h23;
        *(uint32_t*)(sOl + mob + d) = l23;
    }
}

// ---------------------------------------------------------------------------
extern "C" void kernel_launch(void* const* d_in, const int* in_sizes, int n_in,
                              void* d_out, int out_size) {
    const float* x = (const float*)d_in[0];
    const float* w_qkv = (const float*)d_in[1];
    const float* b_qkv = (const float*)d_in[2];
    const float* w_proj = (const float*)d_in[3];
    const float* b_proj = (const float*)d_in[4];
    float* out = (float*)d_out;

    static bool attr_done = false;
    if (!attr_done) {
        cudaFuncSetAttribute(gemm_qkv, cudaFuncAttributeMaxDynamicSharedMemorySize, SMEM_DYN);
        cudaFuncSetAttribute(gemm_proj, cudaFuncAttributeMaxDynamicSharedMemorySize, SMEM_DYN);
        cudaFuncSetAttribute(attn_tc, cudaFuncAttributeMaxDynamicSharedMemorySize, AT_SMEM);
        attr_done = true;
    }

    __nv_bfloat16 *pXh, *pXl, *pWqh, *pWql, *pWph, *pWpl;
    cudaGetSymbolAddress((void**)&pXh, sXh);
    cudaGetSymbolAddress((void**)&pXl, sXl);
    cudaGetSymbolAddress((void**)&pWqh, sWqh);
    cudaGetSymbolAddress((void**)&pWql, sWql);
    cudaGetSymbolAddress((void**)&pWph, sWph);
    cudaGetSymbolAddress((void**)&pWpl, sWpl);

    split_plain<<<Msz * Esz / 4 / 256, 256>>>((const float4*)x, (uint2*)pXh, (uint2*)pXl);
    split_w_tr<<<dim3(NQKV / 32, Esz / 32), 256>>>(w_qkv, pWqh, pWql, NQKV);
    split_w_tr<<<dim3(Esz / 32, Esz / 32), 256>>>(w_proj, pWph, pWpl, Esz);
    gemm_qkv<<<dim3(NQKV / 128, Msz / 128), 256, SMEM_DYN>>>(b_qkv);
    attn_tc<<<dim3(Ssz / 64, Bsz * Hsz), 128, AT_SMEM>>>();
    gemm_proj<<<dim3(Esz / 128, Msz / 128), 256, SMEM_DYN>>>(b_proj, out);
}

// round 7
// speedup vs baseline: 5.6089x; 1.1083x over previous
#include <cuda_runtime.h>
#include <cuda_bf16.h>
#include <cstdint>

// Problem constants
#define Bsz 2
#define Ssz 2048
#define Esz 1024
#define Hsz 16
#define HDd 64
#define Msz (Bsz * Ssz)      // 4096
#define NQKV (3 * Esz)       // 3072

// bf16 hi/lo pre-split operands for the dense GEMMs
__device__ __nv_bfloat16 sXh[Msz * Esz], sXl[Msz * Esz];            // [m][k]
__device__ __nv_bfloat16 sWqh[NQKV * Esz], sWql[NQKV * Esz];        // [n][k]
__device__ __nv_bfloat16 sWph[Esz * Esz], sWpl[Esz * Esz];          // [n][k]
__device__ __nv_bfloat16 sOh[Msz * Esz], sOl[Msz * Esz];            // [m][k] merged heads

// bf16 hi/lo head-split Q/K/V: [B*H][S][64] (Q pre-scaled by 0.125)
__device__ __nv_bfloat16 bQh[Bsz * Hsz * Ssz * HDd], bQl[Bsz * Hsz * Ssz * HDd];
__device__ __nv_bfloat16 bKh[Bsz * Hsz * Ssz * HDd], bKl[Bsz * Hsz * Ssz * HDd];
__device__ __nv_bfloat16 bVh[Bsz * Hsz * Ssz * HDd], bVl[Bsz * Hsz * Ssz * HDd];

// ---------------------------------------------------------------------------
// helpers
// ---------------------------------------------------------------------------
__device__ __forceinline__ void split2(float x0, float x1, uint32_t& hi, uint32_t& lo) {
    __nv_bfloat162 h = __floats2bfloat162_rn(x0, x1);
    float r0 = x0 - __bfloat162float(__low2bfloat16(h));
    float r1 = x1 - __bfloat162float(__high2bfloat16(h));
    __nv_bfloat162 l = __floats2bfloat162_rn(r0, r1);
    hi = *(uint32_t*)&h;
    lo = *(uint32_t*)&l;
}

__device__ __forceinline__ void mma16(float* d, const uint32_t* a, const uint32_t* b) {
    asm volatile(
        "mma.sync.aligned.m16n8k16.row.col.f32.bf16.bf16.f32 "
        "{%0,%1,%2,%3}, {%4,%5,%6,%7}, {%8,%9}, {%0,%1,%2,%3};"
        : "+f"(d[0]), "+f"(d[1]), "+f"(d[2]), "+f"(d[3])
        : "r"(a[0]), "r"(a[1]), "r"(a[2]), "r"(a[3]), "r"(b[0]), "r"(b[1]));
}

__device__ __forceinline__ void ldm4(uint32_t* r, uint32_t addr) {
    asm volatile("ldmatrix.sync.aligned.m8n8.x4.shared.b16 {%0,%1,%2,%3}, [%4];"
                 : "=r"(r[0]), "=r"(r[1]), "=r"(r[2]), "=r"(r[3]) : "r"(addr));
}

__device__ __forceinline__ void ldm4t(uint32_t* r, uint32_t addr) {
    asm volatile("ldmatrix.sync.aligned.m8n8.x4.trans.shared.b16 {%0,%1,%2,%3}, [%4];"
                 : "=r"(r[0]), "=r"(r[1]), "=r"(r[2]), "=r"(r[3]) : "r"(addr));
}

__device__ __forceinline__ void cp16(uint32_t dst, const void* src) {
    asm volatile("cp.async.cg.shared.global [%0], [%1], 16;"
                 :: "r"(dst), "l"(src));
}
#define CP_COMMIT() asm volatile("cp.async.commit_group;" ::: "memory")
#define CP_WAIT(n)  asm volatile("cp.async.wait_group %0;" :: "n"(n) : "memory")

__device__ __forceinline__ uint32_t smem_u32(const void* p) {
    uint32_t a;
    asm("{ .reg .u64 t; cvta.to.shared.u64 t, %1; cvt.u32.u64 %0, t; }"
        : "=r"(a) : "l"(p));
    return a;
}

// ---------------------------------------------------------------------------
// Dense GEMM machinery: CTA 128x128, BK=32, 256 threads, pitch-80 smem,
// cp.async double buffer, ldmatrix, bf16x3.
// ---------------------------------------------------------------------------
#define TILE_B 10240            // 128 * 80
#define STAGE_B (4 * TILE_B)    // 40960
#define SMEM_DYN (2 * STAGE_B)  // 81920

__device__ __forceinline__ void load_stage(
    uint32_t sbst, const __nv_bfloat16* Ah, const __nv_bfloat16* Al,
    const __nv_bfloat16* Bh, const __nv_bfloat16* Bl,
    int m0, int n0, int k0, int tid) {
#pragma unroll
    for (int g = 0; g < 2; g++) {
        const int idx = g * 256 + tid;
        const int row = idx >> 2, ch = idx & 3;
        const uint32_t d = sbst + row * 80 + ch * 16;
        const int aoff = (m0 + row) * Esz + k0 + ch * 8;
        const int boff = (n0 + row) * Esz + k0 + ch * 8;
        cp16(d, Ah + aoff);
        cp16(d + TILE_B, Al + aoff);
        cp16(d + 2 * TILE_B, Bh + boff);
        cp16(d + 3 * TILE_B, Bl + boff);
    }
}

__device__ __forceinline__ void mma_stage(float acc[4][4][4], uint32_t sbst,
                                          int wm0, int wn0, int lane) {
    const int laneRowA = ((lane >> 3) & 1) * 8 + (lane & 7);
    const int chA = lane >> 4;
    const int laneRowB = (lane >> 4) * 8 + (lane & 7);
    const int chB = (lane >> 3) & 1;
#pragma unroll
    for (int ks = 0; ks < 2; ks++) {
        uint32_t ah[4][4], al[4][4], bh[2][4], bl[2][4];
#pragma unroll
        for (int i = 0; i < 4; i++) {
            const uint32_t ra =
                sbst + (wm0 + i * 16 + laneRowA) * 80 + (ks * 2 + chA) * 16;
            ldm4(ah[i], ra);
            ldm4(al[i], ra + TILE_B);
        }
#pragma unroll
        for (int jp = 0; jp < 2; jp++) {
            const uint32_t rb = sbst + 2 * TILE_B +
                (wn0 + jp * 16 + laneRowB) * 80 + (ks * 2 + chB) * 16;
            ldm4(bh[jp], rb);
            ldm4(bl[jp], rb + TILE_B);
        }
#pragma unroll
        for (int i = 0; i < 4; i++)
#pragma unroll
            for (int j = 0; j < 4; j++) {
                const uint32_t* BH_ = &bh[j >> 1][(j & 1) * 2];
                const uint32_t* BL_ = &bl[j >> 1][(j & 1) * 2];
                mma16(acc[i][j], ah[i], BH_);
                mma16(acc[i][j], ah[i], BL_);
                mma16(acc[i][j], al[i], BH_);
            }
    }
}

#define GEMM_MAINLOOP(Ah, Al, Bh, Bl)                                        \
    extern __shared__ char dsm[];                                            \
    const uint32_t sb = smem_u32(dsm);                                       \
    const int tid = threadIdx.x;                                             \
    const int wid = tid >> 5, lane = tid & 31;                               \
    const int wm0 = (wid >> 2) * 64, wn0 = (wid & 3) * 32;                   \
    const int m0 = blockIdx.y * 128, n0 = blockIdx.x * 128;                  \
    float acc[4][4][4];                                                      \
    _Pragma("unroll") for (int i = 0; i < 4; i++)                            \
        _Pragma("unroll") for (int j = 0; j < 4; j++)                        \
            _Pragma("unroll") for (int r = 0; r < 4; r++) acc[i][j][r] = 0.f;\
    load_stage(sb, Ah, Al, Bh, Bl, m0, n0, 0, tid);                          \
    CP_COMMIT();                                                             \
    for (int s = 0; s < Esz / 32; s++) {                                     \
        if (s + 1 < Esz / 32) {                                              \
            load_stage(sb + ((s + 1) & 1) * STAGE_B, Ah, Al, Bh, Bl,         \
                       m0, n0, (s + 1) * 32, tid);                           \
            CP_COMMIT();                                                     \
            CP_WAIT(1);                                                      \
        } else {                                                             \
            CP_WAIT(0);                                                      \
        }                                                                    \
        __syncthreads();                                                     \
        mma_stage(acc, sb + (s & 1) * STAGE_B, wm0, wn0, lane);              \
        __syncthreads();                                                     \
    }

// ---------------------------------------------------------------------------
// Kernel 1: qkv GEMM; epilogue writes pre-split bf16 Q/K/V (Q scaled 0.125)
// ---------------------------------------------------------------------------
__global__ __launch_bounds__(256, 2) void gemm_qkv(const float* __restrict__ bias) {
    GEMM_MAINLOOP(sXh, sXl, sWqh, sWql)

    const int g2 = lane >> 2, t2 = lane & 3;
#pragma unroll
    for (int i = 0; i < 4; i++) {
#pragma unroll
        for (int j = 0; j < 4; j++) {
            const int r0 = m0 + wm0 + i * 16 + g2;
            const int c0 = n0 + wn0 + j * 8 + t2 * 2;
            const int part = c0 >> 10, e = c0 & 1023;
            const int hh = e >> 6, d = e & 63;
            __nv_bfloat16 *dh, *dl;
            if (part == 0)      { dh = bQh; dl = bQl; }
            else if (part == 1) { dh = bKh; dl = bKl; }
            else                { dh = bVh; dl = bVl; }
            const float sc = (part == 0) ? 0.125f : 1.f;
            const float bb0 = bias[c0], bb1 = bias[c0 + 1];
            {
                const int b = r0 >> 11, sq = r0 & 2047;
                const int off = (((b << 4) + hh) * Ssz + sq) * HDd + d;
                uint32_t hi, lo;
                split2((acc[i][j][0] + bb0) * sc, (acc[i][j][1] + bb1) * sc, hi, lo);
                *(uint32_t*)(dh + off) = hi;
                *(uint32_t*)(dl + off) = lo;
            }
            {
                const int r1 = r0 + 8;
                const int b = r1 >> 11, sq = r1 & 2047;
                const int off = (((b << 4) + hh) * Ssz + sq) * HDd + d;
                uint32_t hi, lo;
                split2((acc[i][j][2] + bb0) * sc, (acc[i][j][3] + bb1) * sc, hi, lo);
                *(uint32_t*)(dh + off) = hi;
                *(uint32_t*)(dl + off) = lo;
            }
        }
    }
}

// ---------------------------------------------------------------------------
// Kernel 3: proj GEMM -> d_out
// ---------------------------------------------------------------------------
__global__ __launch_bounds__(256, 2) void gemm_proj(const float* __restrict__ bias,
                                                    float* __restrict__ out) {
    GEMM_MAINLOOP(sOh, sOl, sWph, sWpl)

    const int g2 = lane >> 2, t2 = lane & 3;
#pragma unroll
    for (int i = 0; i < 4; i++) {
#pragma unroll
        for (int j = 0; j < 4; j++) {
            const int r0 = m0 + wm0 + i * 16 + g2;
            const int c0 = n0 + wn0 + j * 8 + t2 * 2;
            const float b0 = bias[c0], b1 = bias[c0 + 1];
            float2 v0 = make_float2(acc[i][j][0] + b0, acc[i][j][1] + b1);
            float2 v1 = make_float2(acc[i][j][2] + b0, acc[i][j][3] + b1);
            *(float2*)(out + r0 * Esz + c0) = v0;
            *(float2*)(out + (r0 + 8) * Esz + c0) = v1;
        }
    }
}

// ---------------------------------------------------------------------------
// Pre-split kernels (X, weights)
// ---------------------------------------------------------------------------
__global__ __launch_bounds__(256) void split_plain(const float4* __restrict__ src,
                                                   uint2* __restrict__ h2,
                                                   uint2* __restrict__ l2) {
    const int i = blockIdx.x * 256 + threadIdx.x;
    const float4 v = src[i];
    uint32_t h0, l0, h1, l1;
    split2(v.x, v.y, h0, l0);
    split2(v.z, v.w, h1, l1);
    h2[i] = make_uint2(h0, h1);
    l2[i] = make_uint2(l0, l1);
}

__global__ __launch_bounds__(256) void split_w_tr(const float* __restrict__ W,
                                                  __nv_bfloat16* __restrict__ Th,
                                                  __nv_bfloat16* __restrict__ Tl,
                                                  int N) {
    __shared__ float t[32][33];
    const int k0 = blockIdx.y * 32, n0 = blockIdx.x * 32;
    const int tx = threadIdx.x & 31, ty = threadIdx.x >> 5;
#pragma unroll
    for (int r = ty; r < 32; r += 8)
        t[r][tx] = W[(k0 + r) * N + n0 + tx];
    __syncthreads();
#pragma unroll
    for (int r = ty; r < 32; r += 8) {
        const float v = t[tx][r];
        __nv_bfloat16 h = __float2bfloat16_rn(v);
        __nv_bfloat16 l = __float2bfloat16_rn(v - __bfloat162float(h));
        Th[(n0 + r) * Esz + k0 + tx] = h;
        Tl[(n0 + r) * Esz + k0 + tx] = l;
    }
}

// ---------------------------------------------------------------------------
// Kernel 2: tensor-core causal flash attention.
// grid = (32 q-tiles, 32 bh), 128 threads. Heavy q-tiles launched first.
// ---------------------------------------------------------------------------
#define AT_PITCH 144
#define AT_TILE (64 * AT_PITCH)              // 9216
#define AT_STAGE0 (2 * AT_TILE)              // Q hi/lo before stages
#define AT_STAGE_B (4 * AT_TILE)             // 36864
#define AT_SMEM (AT_STAGE0 + 2 * AT_STAGE_B) // 92160

__device__ __forceinline__ void at_load_kv(uint32_t st, int base, int kv0, int tid) {
#pragma unroll
    for (int gq = 0; gq < 4; gq++) {
        const int idx = gq * 128 + tid;          // 0..511
        const int row = idx >> 3, ch = idx & 7;
        const uint32_t d = st + row * AT_PITCH + ch * 16;
        const int off = base + (kv0 + row) * HDd + ch * 8;
        cp16(d, bKh + off);
        cp16(d + AT_TILE, bKl + off);
        cp16(d + 2 * AT_TILE, bVh + off);
        cp16(d + 3 * AT_TILE, bVl + off);
    }
}

__global__ __launch_bounds__(128, 2) void attn_tc() {
    extern __shared__ char dsm[];
    const uint32_t sb = smem_u32(dsm);
    const int tid = threadIdx.x, wid = tid >> 5, lane = tid & 31;
    const int bh = blockIdx.y;
    const int q0 = (gridDim.x - 1 - blockIdx.x) * 64;  // heavy tiles first
    const int wq0 = wid * 16;
    const int g = lane >> 2, t = lane & 3;
    const int base = bh * Ssz * HDd;

    // async: Q tile hi/lo
#pragma unroll
    for (int gq = 0; gq < 4; gq++) {
        const int idx = gq * 128 + tid;
        const int row = idx >> 3, ch = idx & 7;
        const uint32_t d = sb + row * AT_PITCH + ch * 16;
        const int off = base + (q0 + row) * HDd + ch * 8;
        cp16(d, bQh + off);
        cp16(d + AT_TILE, bQl + off);
    }
    at_load_kv(sb + AT_STAGE0, base, 0, tid);
    CP_COMMIT();

    const int T = q0 / 64 + 1;

    float oacc[8][4];
#pragma unroll
    for (int j = 0; j < 8; j++)
#pragma unroll
        for (int r = 0; r < 4; r++) oacc[j][r] = 0.f;
    float m_a = -1e30f, m_b = -1e30f, l_a = 0.f, l_b = 0.f;
    uint32_t qh[4][4], ql[4][4];

    const int laneRowB = (lane >> 4) * 8 + (lane & 7);
    const int chB = (lane >> 3) & 1;

    for (int tt = 0; tt < T; tt++) {
        if (tt + 1 < T) {
            at_load_kv(sb + AT_STAGE0 + ((tt + 1) & 1) * AT_STAGE_B,
                       base, (tt + 1) * 64, tid);
            CP_COMMIT();
            CP_WAIT(1);
        } else {
            CP_WAIT(0);
        }
        __syncthreads();

        if (tt == 0) {
#pragma unroll
            for (int ks = 0; ks < 4; ks++) {
                const uint32_t ra = sb + (wq0 + (lane & 15)) * AT_PITCH +
                                    (ks * 2 + (lane >> 4)) * 16;
                ldm4(qh[ks], ra);
                ldm4(ql[ks], ra + AT_TILE);
            }
        }

        const uint32_t st = sb + AT_STAGE0 + (tt & 1) * AT_STAGE_B;

        // S = Q K^T (bf16x3)
        float sacc[8][4];
#pragma unroll
        for (int j = 0; j < 8; j++)
#pragma unroll
            for (int r = 0; r < 4; r++) sacc[j][r] = 0.f;

#pragma unroll
        for (int jp = 0; jp < 4; jp++) {
#pragma unroll
            for (int ks = 0; ks < 4; ks++) {
                const uint32_t rb = st + (jp * 16 + laneRowB) * AT_PITCH +
                                    (ks * 2 + chB) * 16;
                uint32_t kh4[4], kl4[4];
                ldm4(kh4, rb);
                ldm4(kl4, rb + AT_TILE);
                mma16(sacc[jp * 2], qh[ks], &kh4[0]);
                mma16(sacc[jp * 2], qh[ks], &kl4[0]);
                mma16(sacc[jp * 2], ql[ks], &kh4[0]);
                mma16(sacc[jp * 2 + 1], qh[ks], &kh4[2]);
                mma16(sacc[jp * 2 + 1], qh[ks], &kl4[2]);
                mma16(sacc[jp * 2 + 1], ql[ks], &kh4[2]);
            }
        }

        const int rowa = q0 + wq0 + g;
        const int rowb = rowa + 8;

        // causal mask (diagonal tile only)
        if (tt == T - 1) {
            const int kvb = tt * 64;
#pragma unroll
            for (int j = 0; j < 8; j++) {
                const int c0 = kvb + j * 8 + t * 2;
                if (c0 > rowa) sacc[j][0] = -1e30f;
                if (c0 + 1 > rowa) sacc[j][1] = -1e30f;
                if (c0 > rowb) sacc[j][2] = -1e30f;
                if (c0 + 1 > rowb) sacc[j][3] = -1e30f;
            }
        }

        // online softmax
        float mxa = -1e30f, mxb = -1e30f;
#pragma unroll
        for (int j = 0; j < 8; j++) {
            mxa = fmaxf(mxa, fmaxf(sacc[j][0], sacc[j][1]));
            mxb = fmaxf(mxb, fmaxf(sacc[j][2], sacc[j][3]));
        }
        mxa = fmaxf(mxa, __shfl_xor_sync(0xffffffffu, mxa, 1));
        mxa = fmaxf(mxa, __shfl_xor_sync(0xffffffffu, mxa, 2));
        mxb = fmaxf(mxb, __shfl_xor_sync(0xffffffffu, mxb, 1));
        mxb = fmaxf(mxb, __shfl_xor_sync(0xffffffffu, mxb, 2));
        const float mna = fmaxf(m_a, mxa), mnb = fmaxf(m_b, mxb);
        const float ca = __expf(m_a - mna), cb = __expf(m_b - mnb);
        m_a = mna;
        m_b = mnb;

        float ra = 0.f, rb = 0.f;
        uint32_t ph[4][4], pl[4][4];
#pragma unroll
        for (int j = 0; j < 8; j++) {
            const float p0 = __expf(sacc[j][0] - mna);
            const float p1 = __expf(sacc[j][1] - mna);
            const float p2 = __expf(sacc[j][2] - mnb);
            const float p3 = __expf(sacc[j][3] - mnb);
            ra += p0 + p1;
            rb += p2 + p3;
            uint32_t h01, l01, h23, l23;
            split2(p0, p1, h01, l01);
            split2(p2, p3, h23, l23);
            const int ks = j >> 1, half = (j & 1) * 2;
            ph[ks][half] = h01;
            ph[ks][half + 1] = h23;
            pl[ks][half] = l01;
            pl[ks][half + 1] = l23;
        }
        ra += __shfl_xor_sync(0xffffffffu, ra, 1);
        ra += __shfl_xor_sync(0xffffffffu, ra, 2);
        rb += __shfl_xor_sync(0xffffffffu, rb, 1);
        rb += __shfl_xor_sync(0xffffffffu, rb, 2);
        l_a = l_a * ca + ra;
        l_b = l_b * cb + rb;

#pragma unroll
        for (int j = 0; j < 8; j++) {
            oacc[j][0] *= ca;
            oacc[j][1] *= ca;
            oacc[j][2] *= cb;
            oacc[j][3] *= cb;
        }

        // O += P V (bf16x3), V via trans-ldmatrix
        const uint32_t vbase = st + 2 * AT_TILE;
#pragma unroll
        for (int ks = 0; ks < 4; ks++) {
#pragma unroll
            for (int jp = 0; jp < 4; jp++) {
                const uint32_t va = vbase + (ks * 16 + (lane & 15)) * AT_PITCH +
                                    (jp * 16 + (lane >> 4) * 8) * 2;
                uint32_t vh4[4], vl4[4];
                ldm4t(vh4, va);
                ldm4t(vl4, va + AT_TILE);
                mma16(oacc[jp * 2], ph[ks], &vh4[0]);
                mma16(oacc[jp * 2], ph[ks], &vl4[0]);
                mma16(oacc[jp * 2], pl[ks], &vh4[0]);
                mma16(oacc[jp * 2 + 1], ph[ks], &vh4[2]);
                mma16(oacc[jp * 2 + 1], ph[ks], &vl4[2]);
                mma16(oacc[jp * 2 + 1], pl[ks], &vh4[2]);
            }
        }
        __syncthreads();
    }

    // normalize + write merged-head pre-split output
    const float ia = 1.f / l_a, ib = 1.f / l_b;
    const int b = bh >> 4, h = bh & 15;
    const int rowa = q0 + wq0 + g;
    const int moa = (b * Ssz + rowa) * Esz + h * HDd;
    const int mob = (b * Ssz + rowa + 8) * Esz + h * HDd;
#pragma unroll
    for (int j = 0; j < 8; j++) {
        const int d = j * 8 + t * 2;
        uint32_t h01, l01, h23, l23;
        split2(oacc[j][0] * ia, oacc[j][1] * ia, h01, l01);
        split2(oacc[j][2] * ib, oacc[j][3] * ib, h23, l23);
        *(uint32_t*)(sOh + moa + d) = h01;
        *(uint32_t*)(sOl + moa + d) = l01;
        *(uint32_t*)(sOh + mob + d) = h23;
        *(uint32_t*)(sOl + mob + d) = l23;
    }
}

// ---------------------------------------------------------------------------
extern "C" void kernel_launch(void* const* d_in, const int* in_sizes, int n_in,
                              void* d_out, int out_size) {
    const float* x = (const float*)d_in[0];
    const float* w_qkv = (const float*)d_in[1];
    const float* b_qkv = (const float*)d_in[2];
    const float* w_proj = (const float*)d_in[3];
    const float* b_proj = (const float*)d_in[4];
    float* out = (float*)d_out;

    static bool attr_done = false;
    if (!attr_done) {
        cudaFuncSetAttribute(gemm_qkv, cudaFuncAttributeMaxDynamicSharedMemorySize, SMEM_DYN);
        cudaFuncSetAttribute(gemm_proj, cudaFuncAttributeMaxDynamicSharedMemorySize, SMEM_DYN);
        cudaFuncSetAttribute(attn_tc, cudaFuncAttributeMaxDynamicSharedMemorySize, AT_SMEM);
        attr_done = true;
    }

    __nv_bfloat16 *pXh, *pXl, *pWqh, *pWql, *pWph, *pWpl;
    cudaGetSymbolAddress((void**)&pXh, sXh);
    cudaGetSymbolAddress((void**)&pXl, sXl);
    cudaGetSymbolAddress((void**)&pWqh, sWqh);
    cudaGetSymbolAddress((void**)&pWql, sWql);
    cudaGetSymbolAddress((void**)&pWph, sWph);
    cudaGetSymbolAddress((void**)&pWpl, sWpl);

    split_plain<<<Msz * Esz / 4 / 256, 256>>>((const float4*)x, (uint2*)pXh, (uint2*)pXl);
    split_w_tr<<<dim3(NQKV / 32, Esz / 32), 256>>>(w_qkv, pWqh, pWql, NQKV);
    split_w_tr<<<dim3(Esz / 32, Esz / 32), 256>>>(w_proj, pWph, pWpl, Esz);
    gemm_qkv<<<dim3(NQKV / 128, Msz / 128), 256, SMEM_DYN>>>(b_qkv);
    attn_tc<<<dim3(Ssz / 64, Bsz * Hsz), 128, AT_SMEM>>>();
    gemm_proj<<<dim3(Esz / 128, Msz / 128), 256, SMEM_DYN>>>(b_proj, out);
}